// round 12
// baseline (speedup 1.0000x reference)
#include <cuda_runtime.h>
#include <cuda_fp16.h>
#include <cstdint>
#include <math.h>

#define Bsz 2
#define Lseq 4096
#define DM 768
#define DS 16
#define EE 1536
#define NROWS (Bsz*Lseq)      // 8192
#define KCAT 1600             // 1536 (xact) + 16 (us) + 48 (zero pad)
#define KC_CAT 100            // KCAT/16
#define KC_CAT64 25           // KCAT/64
#define LN_EPS 1e-5f
#define XD_ZS 4               // K-split factor for small proj

#define STAGE_BYTES 32768     // A tile 16KB + B tile 16KB (K-chunk 64, fp16)
#define GEMM_SMEM (3 * STAGE_BYTES)

// prep kernel block-region boundaries
#define NB_WIN  4608          // EE*DM/256
#define NB_WOL  (NB_WIN + 2304)
#define NB_XPL  (NB_WOL + 4608)
#define NB_WPS  (NB_XPL + 768)
#define NB_WUS2 (NB_WPS + 24)
#define NB_CB   (NB_WUS2 + 3)

// ======================= small PTX helpers ==================================
__device__ __forceinline__ uint32_t smem_u32(const void* p) {
    uint32_t a;
    asm("{ .reg .u64 t; cvta.to.shared.u64 t, %1; cvt.u32.u64 %0, t; }"
        : "=r"(a) : "l"(p));
    return a;
}
__device__ __forceinline__ void cp_async16(uint32_t dst, const void* src) {
    asm volatile("cp.async.cg.shared.global [%0], [%1], 16;"
                 :: "r"(dst), "l"(src) : "memory");
}
__device__ __forceinline__ void cp_commit() {
    asm volatile("cp.async.commit_group;" ::: "memory");
}
template<int N> __device__ __forceinline__ void cp_wait() {
    asm volatile("cp.async.wait_group %0;" :: "n"(N) : "memory");
}
__device__ __forceinline__ void mma_f16(float* c, const uint32_t* a, const uint32_t* b) {
    asm volatile("mma.sync.aligned.m16n8k16.row.col.f32.f16.f16.f32 "
        "{%0,%1,%2,%3}, {%4,%5,%6,%7}, {%8,%9}, {%0,%1,%2,%3};"
        : "+f"(c[0]), "+f"(c[1]), "+f"(c[2]), "+f"(c[3])
        : "r"(a[0]), "r"(a[1]), "r"(a[2]), "r"(a[3]), "r"(b[0]), "r"(b[1]));
}

// ---- A fragment-native layout (unchanged, 16-k blocks) ----------------------
__device__ __forceinline__ size_t afh_idx(int r, int k, int KC16) {
    size_t blk = (size_t)((r >> 4) * KC16 + (k >> 4));
    int b32 = (r & 7) * 16 + ((k >> 1) & 3) * 4 + ((r >> 3) & 1) + 2 * ((k >> 3) & 1);
    return blk * 256 + b32 * 2 + (k & 1);
}
__device__ __forceinline__ void afh_inv(int idx, int KC16, int& r, int& k) {
    int blk = idx >> 8;
    int b32 = (idx & 255) >> 1, h = idx & 1;
    r = (blk / KC16) * 16 + ((b32 & 1) << 3) + (b32 >> 4);
    k = ((blk % KC16) << 4) | (((b32 >> 1) & 1) << 3) | (((b32 >> 2) & 3) << 1) | h;
}

// ---- B layout: chunk-level [ng][kc64][n:8][tg:4][kb:4][khalf:2][h] ----------
// One LDS.128 at (n, tg, kb even) yields fragments for kb and kb+1.
__device__ __forceinline__ size_t bfh_idx(int n, int k, int KC64) {
    size_t blk = (size_t)((n >> 3) * KC64 + (k >> 6));
    int b32 = (n & 7) * 32 + ((k >> 1) & 3) * 8 + ((k >> 4) & 3) * 2 + ((k >> 3) & 1);
    return blk * 512 + b32 * 2 + (k & 1);
}
__device__ __forceinline__ void bfh_inv(int idx, int KC64, int& n, int& k) {
    int blk = idx >> 9;
    int w = idx & 511;
    int h = w & 1, b32 = w >> 1;
    int n7 = b32 >> 5, r = b32 & 31;
    int tg = r >> 3, kb = (r >> 1) & 3, khalf = r & 1;
    n = (blk / KC64) * 8 + n7;
    k = ((blk % KC64) << 6) | (kb << 4) | (khalf << 3) | (tg << 1) | h;
}

// ======================= scratch ============================================
__device__ __align__(256) __half g_xn    [NROWS * DM];     // A_f (K=768)
__device__ __align__(256) __half g_xin   [NROWS * EE];     // fp16 row-major
__device__ __align__(256) __half g_cat   [NROWS * KCAT];   // A_f: xact|us|0
__device__ __align__(256) float  g_xd    [XD_ZS * NROWS * 32]; // ds|dt_raw partials
__device__ float g_dt [NROWS * DS];
__device__ float g_bt [NROWS * DS];
__device__ float g_bias32[32];
__device__ float g_cbias [DM];
__device__ __align__(256) __half g_winF  [EE * DM];        // B_f: N=1536, K=768
__device__ __align__(256) __half g_wpsF  [128 * EE];       // B_f: N=128(pad), K=1536
__device__ __align__(256) __half g_xplF  [EE * DM];        // A_f: W_xp_low (M=1536,K=768)
__device__ __align__(256) __half g_wolF  [DM * DM];        // B_f: W_out_low (N=768,K=768)
__device__ __align__(256) __half g_comboF[(DM/8) * KC_CAT64 * 512]; // B_f: N=768, K=1600

// ======================= fp16 mma.sync GEMM (K-chunk 64, 8 warps) ===========
// Block 128x128, warp tile 32x64 (wm=wid>>1, wn=wid&1).
// MODE 0: float row-major out (+bias)   MODE 1: half row-major out (+bias)
// MODE 2: half out in bfh layout (k=row, n=col), += addW for row>=768
// grid.z>1: K split across z; bias only z==0; out += z*zstride bytes.
template<int MODE>
__global__ __launch_bounds__(256, 2) void gemm_f16_kernel(
    const __half* __restrict__ Af, int kc16s,
    const __half* __restrict__ Bf,
    const float* __restrict__ bias, void* __restrict__ Cv,
    int ldc, int Ndim, int K, const float* __restrict__ addW,
    size_t zstride)
{
    extern __shared__ __align__(16) char sm[];
    const int tid = threadIdx.x;
    const int wid = tid >> 5, lane = tid & 31;
    const int wm = wid >> 1, wn = wid & 1;
    const int g = lane >> 2, tg = lane & 3;
    const int KC64 = K >> 6;
    const int NCz = KC64 / gridDim.z;
    const int c0 = blockIdx.z * NCz;
    const int mp0 = blockIdx.y * 8;
    const int ng0 = blockIdx.x * 16;
    const int m0 = blockIdx.y * 128, n0 = blockIdx.x * 128;
    const uint32_t smb = smem_u32(sm);

    auto load_chunk = [&](int i) {
        const int c = c0 + i;
        const uint32_t st = (uint32_t)(i % 3) * STAGE_BYTES;
        #pragma unroll
        for (int j = 0; j < 4; j++) {
            int L = tid + 256 * j;
            int pp = L >> 7, qq = (L >> 5) & 3, ll = L & 31;
            const __half* src = Af + ((size_t)(mp0 + pp) * kc16s + 4 * c + qq) * 256 + ll * 8;
            cp_async16(smb + st + (uint32_t)((pp * 4 + qq) * 512 + ll * 16), src);
        }
        #pragma unroll
        for (int j = 0; j < 4; j++) {
            int L = tid + 256 * j;
            int ng = L >> 6, gr = L & 63;
            const __half* src = Bf + ((size_t)(ng0 + ng) * KC64 + c) * 512 + gr * 8;
            cp_async16(smb + st + 16384u + (uint32_t)(ng * 1024 + gr * 16), src);
        }
        cp_commit();
    };

    float acc[2][8][4];
    #pragma unroll
    for (int mi = 0; mi < 2; mi++)
        #pragma unroll
        for (int ni = 0; ni < 8; ni++)
            #pragma unroll
            for (int q = 0; q < 4; q++) acc[mi][ni][q] = 0.0f;

    load_chunk(0); load_chunk(1);

    const char* stA_w = sm + wm * 4096 + g * 64 + tg * 16;
    const char* stB_w = sm + 16384 + wn * 8192 + g * 128 + tg * 32;

    for (int i = 0; i < NCz; i++) {
        cp_wait<1>();
        __syncthreads();
        if (i + 2 < NCz) load_chunk(i + 2); else cp_commit();

        const char* stA = stA_w + (i % 3) * STAGE_BYTES;
        const char* stB = stB_w + (i % 3) * STAGE_BYTES;

        #pragma unroll
        for (int p = 0; p < 2; p++) {        // kb pairs: (0,1) then (2,3)
            uint4 a0 = *(const uint4*)(stA + (2 * p) * 512);
            uint4 a1 = *(const uint4*)(stA + (2 * p + 1) * 512);
            uint4 a2 = *(const uint4*)(stA + 2048 + (2 * p) * 512);
            uint4 a3 = *(const uint4*)(stA + 2048 + (2 * p + 1) * 512);
            uint4 bq[8];
            #pragma unroll
            for (int ni = 0; ni < 8; ni++)
                bq[ni] = *(const uint4*)(stB + ni * 1024 + p * 16);
            #pragma unroll
            for (int ni = 0; ni < 8; ni++) {
                mma_f16(acc[0][ni], (const uint32_t*)&a0, (const uint32_t*)&bq[ni].x);
                mma_f16(acc[1][ni], (const uint32_t*)&a2, (const uint32_t*)&bq[ni].x);
                mma_f16(acc[0][ni], (const uint32_t*)&a1, (const uint32_t*)&bq[ni].z);
                mma_f16(acc[1][ni], (const uint32_t*)&a3, (const uint32_t*)&bq[ni].z);
            }
        }
    }

    if (MODE == 2) {
        __half* Cc = (__half*)Cv;
        #pragma unroll
        for (int mi = 0; mi < 2; mi++)
            #pragma unroll
            for (int ni = 0; ni < 8; ni++)
                #pragma unroll
                for (int q = 0; q < 4; q++) {
                    int row = m0 + wm * 32 + mi * 16 + g + ((q >> 1) << 3);
                    int col = n0 + wn * 64 + ni * 8 + tg * 2 + (q & 1);
                    float v = acc[mi][ni][q];
                    if (row >= DM) v += addW[(size_t)row * DM + col];
                    Cc[bfh_idx(col, row, KC_CAT64)] = __float2half_rn(v);
                }
    } else {
        const bool ub = (blockIdx.z == 0);
        char* Cz = (char*)Cv + (size_t)blockIdx.z * zstride;
        #pragma unroll
        for (int mi = 0; mi < 2; mi++) {
            const int row = m0 + wm * 32 + mi * 16 + g;
            #pragma unroll
            for (int ni = 0; ni < 8; ni++) {
                const int col = n0 + wn * 64 + ni * 8 + tg * 2;
                if (col < Ndim) {
                    float bx = ub ? bias[col] : 0.0f;
                    float by = ub ? bias[col + 1] : 0.0f;
                    float v00 = acc[mi][ni][0] + bx, v01 = acc[mi][ni][1] + by;
                    float v10 = acc[mi][ni][2] + bx, v11 = acc[mi][ni][3] + by;
                    if (MODE == 1) {
                        __half* c0 = (__half*)Cz + (size_t)row * ldc;
                        __half* c1 = (__half*)Cz + (size_t)(row + 8) * ldc;
                        *(__half2*)(c0 + col) = __floats2half2_rn(v00, v01);
                        *(__half2*)(c1 + col) = __floats2half2_rn(v10, v11);
                    } else {
                        float* c0 = (float*)Cz + (size_t)row * ldc;
                        float* c1 = (float*)Cz + (size_t)(row + 8) * ldc;
                        *(float2*)(c0 + col) = make_float2(v00, v01);
                        *(float2*)(c1 + col) = make_float2(v10, v11);
                    }
                }
            }
        }
    }
}

// ======================= merged weight-prep kernel ==========================
__global__ void prep_kernel(const float* __restrict__ W_in,
                            const float* __restrict__ W_out,
                            const float* __restrict__ W_xp,
                            const float* __restrict__ W_dt,
                            const float* __restrict__ W_us,
                            const float* __restrict__ b_xp,
                            const float* __restrict__ b_dt,
                            const float* __restrict__ b_us,
                            const float* __restrict__ b_out) {
    __shared__ float red[8][16][32];
    const int blk = blockIdx.x;
    const int tid = threadIdx.x;

    if (blk < NB_WIN) {
        int idx = blk * 256 + tid;
        int n, k; bfh_inv(idx, 12, n, k);            // K=768 -> KC64=12
        g_winF[idx] = __float2half_rn(W_in[(size_t)k * EE + n]);
    } else if (blk < NB_WOL) {
        int idx = (blk - NB_WIN) * 256 + tid;
        int n, k; bfh_inv(idx, 12, n, k);
        g_wolF[idx] = __float2half_rn(W_out[(size_t)k * DM + n]);
    } else if (blk < NB_XPL) {
        int idx = (blk - NB_WOL) * 256 + tid;
        int r, k; afh_inv(idx, 48, r, k);
        g_xplF[idx] = __float2half_rn(W_xp[(size_t)r * (DM + DS) + k]);
    } else if (blk < NB_WPS) {
        int idx = (blk - NB_XPL) * 256 + tid;
        int n, k; bfh_inv(idx, 24, n, k);            // K=1536 -> KC64=24
        float v = (n < DS)     ? W_xp[(size_t)k * (DM + DS) + DM + n]
                : (n < 2 * DS) ? W_dt[(size_t)k * DS + (n - DS)]
                : 0.0f;
        g_wpsF[idx] = __float2half_rn(v);
        if (blk == NB_XPL && tid < 32)
            g_bias32[tid] = (tid < DS) ? b_xp[DM + tid] : b_dt[tid - DS];
    } else if (blk < NB_WUS2) {
        int bb = blk - NB_WPS;
        int n = bb * 32 + (tid & 31);
        int chunk = tid >> 5;
        float acc[16];
        #pragma unroll
        for (int s = 0; s < 16; s++) acc[s] = 0.0f;
        for (int j = chunk * 96; j < chunk * 96 + 96; j++) {
            float wo = W_out[(size_t)j * DM + n];
            #pragma unroll
            for (int s = 0; s < 16; s++)
                acc[s] = fmaf(W_us[(size_t)s * DM + j], wo, acc[s]);
        }
        #pragma unroll
        for (int s = 0; s < 16; s++) red[chunk][s][tid & 31] = acc[s];
        __syncthreads();
        for (int o = tid; o < 512; o += 256) {
            int s = o >> 5, ln = o & 31;
            float t = 0.0f;
            #pragma unroll
            for (int c = 0; c < 8; c++) t += red[c][s][ln];
            int nn = bb * 32 + ln;
            g_comboF[bfh_idx(nn, EE + s,          KC_CAT64)] = __float2half_rn(t);
            g_comboF[bfh_idx(nn, EE + DS + s,     KC_CAT64)] = __half(0.0f);
            g_comboF[bfh_idx(nn, EE + 2 * DS + s, KC_CAT64)] = __half(0.0f);
            g_comboF[bfh_idx(nn, EE + 3 * DS + s, KC_CAT64)] = __half(0.0f);
        }
    } else {
        int n = (blk - NB_WUS2) * 256 + tid;
        float acc = b_out[n];
        for (int j = 0; j < DM; j++)
            acc = fmaf(b_xp[j] + b_us[j], W_out[(size_t)j * DM + n], acc);
        g_cbias[n] = acc;
    }
}

// ======================= LayerNorm -> A_f fp16 (K=768), 384 thr =============
__global__ __launch_bounds__(384) void ln_kernel(const float* __restrict__ x,
                                                 const float* __restrict__ g,
                                                 const float* __restrict__ b) {
    int row = blockIdx.x, tid = threadIdx.x;
    const float2* xr = (const float2*)(x + (size_t)row * DM);
    float2 v = xr[tid];
    __shared__ float red[512];
    if (tid < 128) red[384 + tid] = 0.0f;
    red[tid] = v.x + v.y;
    __syncthreads();
    for (int off = 256; off > 0; off >>= 1) {
        if (tid < off) red[tid] += red[tid + off];
        __syncthreads();
    }
    float mu = red[0] * (1.0f / DM);
    __syncthreads();
    float dx = v.x - mu, dy = v.y - mu;
    red[tid] = dx * dx + dy * dy;
    __syncthreads();
    for (int off = 256; off > 0; off >>= 1) {
        if (tid < off) red[tid] += red[tid + off];
        __syncthreads();
    }
    float rstd = rsqrtf(red[0] * (1.0f / DM) + LN_EPS);
    float2 gg = ((const float2*)g)[tid];
    float2 bb = ((const float2*)b)[tid];
    float h0 = dx * rstd * gg.x + bb.x;
    float h1 = dy * rstd * gg.y + bb.y;
    *(__half2*)(g_xn + afh_idx(row, 2 * tid, 48)) = __floats2half2_rn(h0, h1);
}

// ======================= depthwise conv (k=4) + SiLU, channel pairs =========
__global__ void conv_silu_kernel(const float* __restrict__ b_conv,
                                 const float* __restrict__ W_conv) {
    int idx = blockIdx.x * blockDim.x + threadIdx.x;
    if (idx >= (NROWS / 4) * (EE / 2)) return;
    int ep = idx % (EE / 2);
    int e0 = ep * 2;
    int r0 = (idx / (EE / 2)) * 4;
    int l0 = r0 % Lseq;
    const __half2* xin2 = (const __half2*)g_xin;

    float2 xa[7];
    #pragma unroll
    for (int j = 0; j < 3; j++) {
        if (l0 >= 3 - j) xa[j] = __half22float2(xin2[(size_t)(r0 - 3 + j) * (EE/2) + ep]);
        else             xa[j] = make_float2(0.f, 0.f);
    }
    #pragma unroll
    for (int j = 3; j < 7; j++)
        xa[j] = __half22float2(xin2[(size_t)(r0 - 3 + j) * (EE/2) + ep]);

    float4 wA = *(const float4*)(W_conv + e0 * 4);
    float4 wB = *(const float4*)(W_conv + e0 * 4 + 4);
    float bc0 = b_conv[e0], bc1 = b_conv[e0 + 1];

    #pragma unroll
    for (int i = 0; i < 4; i++) {
        float sx = bc0 + xa[i].x * wA.x + xa[i+1].x * wA.y + xa[i+2].x * wA.z + xa[i+3].x * wA.w;
        float sy = bc1 + xa[i].y * wB.x + xa[i+1].y * wB.y + xa[i+2].y * wB.z + xa[i+3].y * wB.w;
        float ax = sx / (1.0f + expf(-sx));
        float ay = sy / (1.0f + expf(-sy));
        *(__half2*)(g_cat + afh_idx(r0 + i, e0, KC_CAT)) = __floats2half2_rn(ax, ay);
    }
}

// ======================= fused prescan + scan + us ==========================
__global__ __launch_bounds__(256) void scan_kernel() {
    int chan = blockIdx.x;
    int bb = chan / DS, s = chan % DS;
    int t = threadIdx.x;
    __shared__ float sA[256], sB[256];
    float A = 1.0f, Bl = 0.0f;
    int base = bb * Lseq;
    #pragma unroll 4
    for (int i = 0; i < 16; i++) {
        size_t rofs = (size_t)(base + t * 16 + i);
        float ds = 0.0f, dtraw = 0.0f;
        #pragma unroll
        for (int z = 0; z < XD_ZS; z++) {
            ds    += g_xd[(size_t)z * NROWS * 32 + rofs * 32 + s];
            dtraw += g_xd[(size_t)z * NROWS * 32 + rofs * 32 + 16 + s];
        }
        float dt = fmaxf(dtraw, 0.0f) + log1pf(expf(-fabsf(dtraw)));
        float bt = ds * expf(-0.5f * dt);
        g_dt[rofs * DS + s] = dt;
        g_bt[rofs * DS + s] = bt;
        float a = expf(-dt);
        Bl = a * Bl + bt;
        A = a * A;
    }
    sA[t] = A; sB[t] = Bl;
    __syncthreads();
    for (int offp = 1; offp < 256; offp <<= 1) {
        float pA = 0.f, pB = 0.f;
        bool has = (t >= offp);
        if (has) { pA = sA[t - offp]; pB = sB[t - offp]; }
        __syncthreads();
        if (has) { sB[t] = sA[t] * pB + sB[t]; sA[t] = sA[t] * pA; }
        __syncthreads();
    }
    float v = (t == 0) ? 0.0f : sB[t - 1];
    for (int i = 0; i < 16; i++) {
        int l = t * 16 + i;
        int row = base + l;
        size_t off = (size_t)row * DS + s;
        float dt = g_dt[off];
        float bt = g_bt[off];
        v = expf(-dt) * v + bt;
        float kf = (float)(Lseq - 1 - l);
        float denom = expm1f(-dt);
        if (denom > -1e-30f) denom = -1e-30f;
        float us = expf(-kf * dt) * v + bt * expm1f(-kf * dt) / denom;
        g_cat[afh_idx(row, EE + s,          KC_CAT)] = __float2half_rn(us);
        g_cat[afh_idx(row, EE + DS + s,     KC_CAT)] = __half(0.0f);
        g_cat[afh_idx(row, EE + 2 * DS + s, KC_CAT)] = __half(0.0f);
        g_cat[afh_idx(row, EE + 3 * DS + s, KC_CAT)] = __half(0.0f);
    }
}

// ======================= launch =============================================
extern "C" void kernel_launch(void* const* d_in, const int* in_sizes, int n_in,
                              void* d_out, int out_size) {
    const float* x      = (const float*)d_in[0];
    const float* ln_g   = (const float*)d_in[1];
    const float* ln_b   = (const float*)d_in[2];
    const float* W_in   = (const float*)d_in[3];
    const float* b_in   = (const float*)d_in[4];
    const float* W_conv = (const float*)d_in[5];
    const float* b_conv = (const float*)d_in[6];
    const float* W_xp   = (const float*)d_in[7];
    const float* b_xp   = (const float*)d_in[8];
    const float* W_dt   = (const float*)d_in[9];
    const float* b_dt   = (const float*)d_in[10];
    const float* W_us   = (const float*)d_in[11];
    const float* b_us   = (const float*)d_in[12];
    const float* W_out  = (const float*)d_in[13];
    const float* b_out  = (const float*)d_in[14];
    float* out = (float*)d_out;

    __half *xn, *xin, *cat, *winF, *wpsF, *xplF, *wolF, *comboF;
    float *xd, *bias32, *cbias;
    cudaGetSymbolAddress((void**)&xn,     g_xn);
    cudaGetSymbolAddress((void**)&xin,    g_xin);
    cudaGetSymbolAddress((void**)&cat,    g_cat);
    cudaGetSymbolAddress((void**)&xd,     g_xd);
    cudaGetSymbolAddress((void**)&bias32, g_bias32);
    cudaGetSymbolAddress((void**)&cbias,  g_cbias);
    cudaGetSymbolAddress((void**)&winF,   g_winF);
    cudaGetSymbolAddress((void**)&wpsF,   g_wpsF);
    cudaGetSymbolAddress((void**)&xplF,   g_xplF);
    cudaGetSymbolAddress((void**)&wolF,   g_wolF);
    cudaGetSymbolAddress((void**)&comboF, g_comboF);

    cudaFuncSetAttribute(gemm_f16_kernel<0>, cudaFuncAttributeMaxDynamicSharedMemorySize, GEMM_SMEM);
    cudaFuncSetAttribute(gemm_f16_kernel<1>, cudaFuncAttributeMaxDynamicSharedMemorySize, GEMM_SMEM);
    cudaFuncSetAttribute(gemm_f16_kernel<2>, cudaFuncAttributeMaxDynamicSharedMemorySize, GEMM_SMEM);

    // 1. merged weight prep
    prep_kernel<<<NB_CB, 256>>>(W_in, W_out, W_xp, W_dt, W_us,
                                b_xp, b_dt, b_us, b_out);

    // 2. W_combo rows [0,1536): xplF @ wolF^T + W_out_hi -> comboF (MODE 2)
    gemm_f16_kernel<2><<<dim3(DM/128, EE/128, 1), 256, GEMM_SMEM>>>(
        xplF, 48, wolF, nullptr, comboF, 0, DM, DM, W_out, 0);

    // 3. LayerNorm -> A_f
    ln_kernel<<<NROWS, 384>>>(x, ln_g, ln_b);

    // 4. in-proj: (8192x768)@(768x1536) -> xin fp16 row-major
    gemm_f16_kernel<1><<<dim3(EE/128, NROWS/128, 1), 256, GEMM_SMEM>>>(
        xn, 48, winF, b_in, xin, EE, EE, DM, nullptr, 0);

    // 5. conv + silu -> g_cat A_f (k-blocks 0..95)
    conv_silu_kernel<<<((NROWS/4) * (EE/2) + 255) / 256, 256>>>(b_conv, W_conv);

    // 6. small proj: (8192x1536)@(1536x32) -> xd, K split over grid.z=4
    gemm_f16_kernel<0><<<dim3(1, NROWS/128, XD_ZS), 256, GEMM_SMEM>>>(
        cat, KC_CAT, wpsF, bias32, xd, 32, 32, EE, nullptr,
        (size_t)NROWS * 32 * sizeof(float));

    // 7. fused prescan + scan + us -> g_cat k-blocks 96..99
    scan_kernel<<<Bsz * DS, 256>>>();

    // 8. final: (8192x1600)@(1600x768) + cbias -> out
    gemm_f16_kernel<0><<<dim3(DM/128, NROWS/128, 1), 256, GEMM_SMEM>>>(
        cat, KC_CAT, comboF, cbias, out, DM, DM, KCAT, nullptr, 0);
}

// round 13
// speedup vs baseline: 1.0722x; 1.0722x over previous
#include <cuda_runtime.h>
#include <cuda_fp16.h>
#include <cstdint>
#include <math.h>

#define Bsz 2
#define Lseq 4096
#define DM 768
#define DS 16
#define EE 1536
#define NROWS (Bsz*Lseq)      // 8192
#define KCAT 1600             // 1536 (xact) + 16 (us) + 48 (zero pad)
#define KC_CAT 100            // KCAT/16
#define KC_CAT64 25           // KCAT/64
#define LN_EPS 1e-5f
#define XD_ZS 4               // K-split factor for small proj

#define STAGE_BYTES 32768     // A tile 16KB + B tile 16KB (K-chunk 64, fp16)
#define GEMM_SMEM (3 * STAGE_BYTES)

// prep kernel block-region boundaries
#define NB_WIN  4608          // EE*DM/256
#define NB_WOL  (NB_WIN + 2304)
#define NB_XPL  (NB_WOL + 4608)
#define NB_WPS  (NB_XPL + 768)
#define NB_WUS2 (NB_WPS + 24)
#define NB_CB   (NB_WUS2 + 3)

// ======================= small PTX helpers ==================================
__device__ __forceinline__ uint32_t smem_u32(const void* p) {
    uint32_t a;
    asm("{ .reg .u64 t; cvta.to.shared.u64 t, %1; cvt.u32.u64 %0, t; }"
        : "=r"(a) : "l"(p));
    return a;
}
__device__ __forceinline__ void cp_async16(uint32_t dst, const void* src) {
    asm volatile("cp.async.cg.shared.global [%0], [%1], 16;"
                 :: "r"(dst), "l"(src) : "memory");
}
__device__ __forceinline__ void cp_commit() {
    asm volatile("cp.async.commit_group;" ::: "memory");
}
template<int N> __device__ __forceinline__ void cp_wait() {
    asm volatile("cp.async.wait_group %0;" :: "n"(N) : "memory");
}
__device__ __forceinline__ void mma_f16(float* c, const uint32_t* a, const uint32_t* b) {
    asm volatile("mma.sync.aligned.m16n8k16.row.col.f32.f16.f16.f32 "
        "{%0,%1,%2,%3}, {%4,%5,%6,%7}, {%8,%9}, {%0,%1,%2,%3};"
        : "+f"(c[0]), "+f"(c[1]), "+f"(c[2]), "+f"(c[3])
        : "r"(a[0]), "r"(a[1]), "r"(a[2]), "r"(a[3]), "r"(b[0]), "r"(b[1]));
}

// ---- A fragment-native layout (16-k blocks) ---------------------------------
__device__ __forceinline__ size_t afh_idx(int r, int k, int KC16) {
    size_t blk = (size_t)((r >> 4) * KC16 + (k >> 4));
    int b32 = (r & 7) * 16 + ((k >> 1) & 3) * 4 + ((r >> 3) & 1) + 2 * ((k >> 3) & 1);
    return blk * 256 + b32 * 2 + (k & 1);
}
__device__ __forceinline__ void afh_inv(int idx, int KC16, int& r, int& k) {
    int blk = idx >> 8;
    int b32 = (idx & 255) >> 1, h = idx & 1;
    r = (blk / KC16) * 16 + ((b32 & 1) << 3) + (b32 >> 4);
    k = ((blk % KC16) << 4) | (((b32 >> 1) & 1) << 3) | (((b32 >> 2) & 3) << 1) | h;
}

// ---- B layout: chunk-blocks of 512 halfs (1024 B), conflict-free interleave -
// addr16(n7,tg,p) = (n7&1) + tg*2 + (n7>>1)*8 + p*32 ; 16B holds kb pair
// {(kb=2p,kh0),(2p,kh1),(2p+1,kh0),(2p+1,kh1)} as 4 b32.
__device__ __forceinline__ size_t bfh_idx(int n, int k, int KC64) {
    size_t blk = (size_t)((n >> 3) * KC64 + (k >> 6));
    int n7 = n & 7, tg = (k >> 1) & 3, p = (k >> 5) & 1;
    int addr16 = (n7 & 1) + tg * 2 + ((n7 >> 1) << 3) + (p << 5);
    int w = (addr16 << 3) + (((k >> 4) & 1) << 2) + (((k >> 3) & 1) << 1) + (k & 1);
    return blk * 512 + w;
}
__device__ __forceinline__ void bfh_inv(int idx, int KC64, int& n, int& k) {
    int blk = idx >> 9;
    int w = idx & 511;
    int h = w & 1;
    int khalf = (w >> 1) & 1;
    int kblow = (w >> 2) & 1;
    int addr16 = w >> 3;
    int p = addr16 >> 5;
    int ghigh = (addr16 >> 3) & 3;
    int tg = (addr16 >> 1) & 3;
    int glow = addr16 & 1;
    n = (blk / KC64) * 8 + ghigh * 2 + glow;
    k = ((blk % KC64) << 6) + (p << 5) + (kblow << 4) + (khalf << 3) + (tg << 1) + h;
}

// ======================= scratch ============================================
__device__ __align__(256) __half g_xn    [NROWS * DM];     // A_f (K=768)
__device__ __align__(256) __half g_xin   [NROWS * EE];     // fp16 row-major
__device__ __align__(256) __half g_cat   [NROWS * KCAT];   // A_f: xact|us|0
__device__ __align__(256) float  g_xd    [XD_ZS * NROWS * 32]; // ds|dt_raw partials
__device__ float g_dt [NROWS * DS];
__device__ float g_bt [NROWS * DS];
__device__ float g_bias32[32];
__device__ float g_cbias [DM];
__device__ __align__(256) __half g_winF  [EE * DM];        // B_f: N=1536, K=768
__device__ __align__(256) __half g_wpsF  [128 * EE];       // B_f: N=128(pad), K=1536
__device__ __align__(256) __half g_xplF  [EE * DM];        // A_f: W_xp_low (M=1536,K=768)
__device__ __align__(256) __half g_wolF  [DM * DM];        // B_f: W_out_low (N=768,K=768)
__device__ __align__(256) __half g_comboF[(DM/8) * KC_CAT64 * 512]; // B_f: N=768, K=1600

// ======================= fp16 mma.sync GEMM (K-chunk 64, 8 warps) ===========
// Block 128x128, warp tile 32x64 (wm=wid>>1, wn=wid&1).
// MODE 0: float row-major out (+bias)   MODE 1: half row-major out (+bias)
// MODE 2: half out in bfh layout (k=row, n=col), += addW for row>=768
// grid.z>1: K split across z; bias only z==0; out += z*zstride bytes.
template<int MODE>
__global__ __launch_bounds__(256, 2) void gemm_f16_kernel(
    const __half* __restrict__ Af, int kc16s,
    const __half* __restrict__ Bf,
    const float* __restrict__ bias, void* __restrict__ Cv,
    int ldc, int Ndim, int K, const float* __restrict__ addW,
    size_t zstride)
{
    extern __shared__ __align__(16) char sm[];
    const int tid = threadIdx.x;
    const int wid = tid >> 5, lane = tid & 31;
    const int wm = wid >> 1, wn = wid & 1;
    const int g = lane >> 2, tg = lane & 3;
    const int KC64 = K >> 6;
    const int NCz = KC64 / gridDim.z;
    const int c0 = blockIdx.z * NCz;
    const int mp0 = blockIdx.y * 8;
    const int ng0 = blockIdx.x * 16;
    const int m0 = blockIdx.y * 128, n0 = blockIdx.x * 128;
    const uint32_t smb = smem_u32(sm);

    auto load_chunk = [&](int i) {
        const int c = c0 + i;
        const uint32_t st = (uint32_t)(i % 3) * STAGE_BYTES;
        #pragma unroll
        for (int j = 0; j < 4; j++) {
            int L = tid + 256 * j;
            int pp = L >> 7, qq = (L >> 5) & 3, ll = L & 31;
            const __half* src = Af + ((size_t)(mp0 + pp) * kc16s + 4 * c + qq) * 256 + ll * 8;
            cp_async16(smb + st + (uint32_t)((pp * 4 + qq) * 512 + ll * 16), src);
        }
        #pragma unroll
        for (int j = 0; j < 4; j++) {
            int L = tid + 256 * j;
            int ng = L >> 6, gr = L & 63;
            const __half* src = Bf + ((size_t)(ng0 + ng) * KC64 + c) * 512 + gr * 8;
            cp_async16(smb + st + 16384u + (uint32_t)(ng * 1024 + gr * 16), src);
        }
        cp_commit();
    };

    float acc[2][8][4];
    #pragma unroll
    for (int mi = 0; mi < 2; mi++)
        #pragma unroll
        for (int ni = 0; ni < 8; ni++)
            #pragma unroll
            for (int q = 0; q < 4; q++) acc[mi][ni][q] = 0.0f;

    load_chunk(0); load_chunk(1);

    const char* stA_w = sm + wm * 4096 + g * 64 + tg * 16;
    const char* stB_w = sm + 16384 + wn * 8192
                      + ((g & 1) + tg * 2) * 16 + (g >> 1) * 128;

    for (int i = 0; i < NCz; i++) {
        cp_wait<1>();
        __syncthreads();
        if (i + 2 < NCz) load_chunk(i + 2); else cp_commit();

        const char* stA = stA_w + (i % 3) * STAGE_BYTES;
        const char* stB = stB_w + (i % 3) * STAGE_BYTES;

        #pragma unroll
        for (int p = 0; p < 2; p++) {        // kb pairs: (0,1) then (2,3)
            uint4 a0 = *(const uint4*)(stA + (2 * p) * 512);
            uint4 a1 = *(const uint4*)(stA + (2 * p + 1) * 512);
            uint4 a2 = *(const uint4*)(stA + 2048 + (2 * p) * 512);
            uint4 a3 = *(const uint4*)(stA + 2048 + (2 * p + 1) * 512);
            uint4 bq[8];
            #pragma unroll
            for (int ni = 0; ni < 8; ni++)
                bq[ni] = *(const uint4*)(stB + ni * 1024 + p * 512);
            #pragma unroll
            for (int ni = 0; ni < 8; ni++) {
                mma_f16(acc[0][ni], (const uint32_t*)&a0, (const uint32_t*)&bq[ni].x);
                mma_f16(acc[1][ni], (const uint32_t*)&a2, (const uint32_t*)&bq[ni].x);
                mma_f16(acc[0][ni], (const uint32_t*)&a1, (const uint32_t*)&bq[ni].z);
                mma_f16(acc[1][ni], (const uint32_t*)&a3, (const uint32_t*)&bq[ni].z);
            }
        }
    }

    if (MODE == 2) {
        __half* Cc = (__half*)Cv;
        #pragma unroll
        for (int mi = 0; mi < 2; mi++)
            #pragma unroll
            for (int ni = 0; ni < 8; ni++)
                #pragma unroll
                for (int q = 0; q < 4; q++) {
                    int row = m0 + wm * 32 + mi * 16 + g + ((q >> 1) << 3);
                    int col = n0 + wn * 64 + ni * 8 + tg * 2 + (q & 1);
                    float v = acc[mi][ni][q];
                    if (row >= DM) v += addW[(size_t)row * DM + col];
                    Cc[bfh_idx(col, row, KC_CAT64)] = __float2half_rn(v);
                }
    } else {
        const bool ub = (blockIdx.z == 0);
        char* Cz = (char*)Cv + (size_t)blockIdx.z * zstride;
        #pragma unroll
        for (int mi = 0; mi < 2; mi++) {
            const int row = m0 + wm * 32 + mi * 16 + g;
            #pragma unroll
            for (int ni = 0; ni < 8; ni++) {
                const int col = n0 + wn * 64 + ni * 8 + tg * 2;
                if (col < Ndim) {
                    float bx = ub ? bias[col] : 0.0f;
                    float by = ub ? bias[col + 1] : 0.0f;
                    float v00 = acc[mi][ni][0] + bx, v01 = acc[mi][ni][1] + by;
                    float v10 = acc[mi][ni][2] + bx, v11 = acc[mi][ni][3] + by;
                    if (MODE == 1) {
                        __half* c0 = (__half*)Cz + (size_t)row * ldc;
                        __half* c1 = (__half*)Cz + (size_t)(row + 8) * ldc;
                        *(__half2*)(c0 + col) = __floats2half2_rn(v00, v01);
                        *(__half2*)(c1 + col) = __floats2half2_rn(v10, v11);
                    } else {
                        float* c0 = (float*)Cz + (size_t)row * ldc;
                        float* c1 = (float*)Cz + (size_t)(row + 8) * ldc;
                        *(float2*)(c0 + col) = make_float2(v00, v01);
                        *(float2*)(c1 + col) = make_float2(v10, v11);
                    }
                }
            }
        }
    }
}

// ======================= merged weight-prep kernel ==========================
__global__ void prep_kernel(const float* __restrict__ W_in,
                            const float* __restrict__ W_out,
                            const float* __restrict__ W_xp,
                            const float* __restrict__ W_dt,
                            const float* __restrict__ W_us,
                            const float* __restrict__ b_xp,
                            const float* __restrict__ b_dt,
                            const float* __restrict__ b_us,
                            const float* __restrict__ b_out) {
    __shared__ float red[8][16][32];
    const int blk = blockIdx.x;
    const int tid = threadIdx.x;

    if (blk < NB_WIN) {
        int idx = blk * 256 + tid;
        int n, k; bfh_inv(idx, 12, n, k);            // K=768 -> KC64=12
        g_winF[idx] = __float2half_rn(W_in[(size_t)k * EE + n]);
    } else if (blk < NB_WOL) {
        int idx = (blk - NB_WIN) * 256 + tid;
        int n, k; bfh_inv(idx, 12, n, k);
        g_wolF[idx] = __float2half_rn(W_out[(size_t)k * DM + n]);
    } else if (blk < NB_XPL) {
        int idx = (blk - NB_WOL) * 256 + tid;
        int r, k; afh_inv(idx, 48, r, k);
        g_xplF[idx] = __float2half_rn(W_xp[(size_t)r * (DM + DS) + k]);
    } else if (blk < NB_WPS) {
        int idx = (blk - NB_XPL) * 256 + tid;
        int n, k; bfh_inv(idx, 24, n, k);            // K=1536 -> KC64=24
        float v = (n < DS)     ? W_xp[(size_t)k * (DM + DS) + DM + n]
                : (n < 2 * DS) ? W_dt[(size_t)k * DS + (n - DS)]
                : 0.0f;
        g_wpsF[idx] = __float2half_rn(v);
        if (blk == NB_XPL && tid < 32)
            g_bias32[tid] = (tid < DS) ? b_xp[DM + tid] : b_dt[tid - DS];
    } else if (blk < NB_WUS2) {
        int bb = blk - NB_WPS;
        int n = bb * 32 + (tid & 31);
        int chunk = tid >> 5;
        float acc[16];
        #pragma unroll
        for (int s = 0; s < 16; s++) acc[s] = 0.0f;
        for (int j = chunk * 96; j < chunk * 96 + 96; j++) {
            float wo = W_out[(size_t)j * DM + n];
            #pragma unroll
            for (int s = 0; s < 16; s++)
                acc[s] = fmaf(W_us[(size_t)s * DM + j], wo, acc[s]);
        }
        #pragma unroll
        for (int s = 0; s < 16; s++) red[chunk][s][tid & 31] = acc[s];
        __syncthreads();
        for (int o = tid; o < 512; o += 256) {
            int s = o >> 5, ln = o & 31;
            float t = 0.0f;
            #pragma unroll
            for (int c = 0; c < 8; c++) t += red[c][s][ln];
            int nn = bb * 32 + ln;
            g_comboF[bfh_idx(nn, EE + s,          KC_CAT64)] = __float2half_rn(t);
            g_comboF[bfh_idx(nn, EE + DS + s,     KC_CAT64)] = __half(0.0f);
            g_comboF[bfh_idx(nn, EE + 2 * DS + s, KC_CAT64)] = __half(0.0f);
            g_comboF[bfh_idx(nn, EE + 3 * DS + s, KC_CAT64)] = __half(0.0f);
        }
    } else {
        int n = (blk - NB_WUS2) * 256 + tid;
        float acc = b_out[n];
        for (int j = 0; j < DM; j++)
            acc = fmaf(b_xp[j] + b_us[j], W_out[(size_t)j * DM + n], acc);
        g_cbias[n] = acc;
    }
}

// ======================= LayerNorm -> A_f fp16 (K=768), 384 thr =============
__global__ __launch_bounds__(384) void ln_kernel(const float* __restrict__ x,
                                                 const float* __restrict__ g,
                                                 const float* __restrict__ b) {
    int row = blockIdx.x, tid = threadIdx.x;
    const float2* xr = (const float2*)(x + (size_t)row * DM);
    float2 v = xr[tid];
    __shared__ float red[512];
    if (tid < 128) red[384 + tid] = 0.0f;
    red[tid] = v.x + v.y;
    __syncthreads();
    for (int off = 256; off > 0; off >>= 1) {
        if (tid < off) red[tid] += red[tid + off];
        __syncthreads();
    }
    float mu = red[0] * (1.0f / DM);
    __syncthreads();
    float dx = v.x - mu, dy = v.y - mu;
    red[tid] = dx * dx + dy * dy;
    __syncthreads();
    for (int off = 256; off > 0; off >>= 1) {
        if (tid < off) red[tid] += red[tid + off];
        __syncthreads();
    }
    float rstd = rsqrtf(red[0] * (1.0f / DM) + LN_EPS);
    float2 gg = ((const float2*)g)[tid];
    float2 bb = ((const float2*)b)[tid];
    float h0 = dx * rstd * gg.x + bb.x;
    float h1 = dy * rstd * gg.y + bb.y;
    *(__half2*)(g_xn + afh_idx(row, 2 * tid, 48)) = __floats2half2_rn(h0, h1);
}

// ======================= depthwise conv (k=4) + SiLU, channel pairs =========
__global__ void conv_silu_kernel(const float* __restrict__ b_conv,
                                 const float* __restrict__ W_conv) {
    int idx = blockIdx.x * blockDim.x + threadIdx.x;
    if (idx >= (NROWS / 4) * (EE / 2)) return;
    int ep = idx % (EE / 2);
    int e0 = ep * 2;
    int r0 = (idx / (EE / 2)) * 4;
    int l0 = r0 % Lseq;
    const __half2* xin2 = (const __half2*)g_xin;

    float2 xa[7];
    #pragma unroll
    for (int j = 0; j < 3; j++) {
        if (l0 >= 3 - j) xa[j] = __half22float2(xin2[(size_t)(r0 - 3 + j) * (EE/2) + ep]);
        else             xa[j] = make_float2(0.f, 0.f);
    }
    #pragma unroll
    for (int j = 3; j < 7; j++)
        xa[j] = __half22float2(xin2[(size_t)(r0 - 3 + j) * (EE/2) + ep]);

    float4 wA = *(const float4*)(W_conv + e0 * 4);
    float4 wB = *(const float4*)(W_conv + e0 * 4 + 4);
    float bc0 = b_conv[e0], bc1 = b_conv[e0 + 1];

    #pragma unroll
    for (int i = 0; i < 4; i++) {
        float sx = bc0 + xa[i].x * wA.x + xa[i+1].x * wA.y + xa[i+2].x * wA.z + xa[i+3].x * wA.w;
        float sy = bc1 + xa[i].y * wB.x + xa[i+1].y * wB.y + xa[i+2].y * wB.z + xa[i+3].y * wB.w;
        float ax = sx / (1.0f + expf(-sx));
        float ay = sy / (1.0f + expf(-sy));
        *(__half2*)(g_cat + afh_idx(r0 + i, e0, KC_CAT)) = __floats2half2_rn(ax, ay);
    }
}

// ======================= fused prescan + scan + us ==========================
__global__ __launch_bounds__(256) void scan_kernel() {
    int chan = blockIdx.x;
    int bb = chan / DS, s = chan % DS;
    int t = threadIdx.x;
    __shared__ float sA[256], sB[256];
    float A = 1.0f, Bl = 0.0f;
    int base = bb * Lseq;
    #pragma unroll 4
    for (int i = 0; i < 16; i++) {
        size_t rofs = (size_t)(base + t * 16 + i);
        float ds = 0.0f, dtraw = 0.0f;
        #pragma unroll
        for (int z = 0; z < XD_ZS; z++) {
            ds    += g_xd[(size_t)z * NROWS * 32 + rofs * 32 + s];
            dtraw += g_xd[(size_t)z * NROWS * 32 + rofs * 32 + 16 + s];
        }
        float dt = fmaxf(dtraw, 0.0f) + log1pf(expf(-fabsf(dtraw)));
        float bt = ds * expf(-0.5f * dt);
        g_dt[rofs * DS + s] = dt;
        g_bt[rofs * DS + s] = bt;
        float a = expf(-dt);
        Bl = a * Bl + bt;
        A = a * A;
    }
    sA[t] = A; sB[t] = Bl;
    __syncthreads();
    for (int offp = 1; offp < 256; offp <<= 1) {
        float pA = 0.f, pB = 0.f;
        bool has = (t >= offp);
        if (has) { pA = sA[t - offp]; pB = sB[t - offp]; }
        __syncthreads();
        if (has) { sB[t] = sA[t] * pB + sB[t]; sA[t] = sA[t] * pA; }
        __syncthreads();
    }
    float v = (t == 0) ? 0.0f : sB[t - 1];
    for (int i = 0; i < 16; i++) {
        int l = t * 16 + i;
        int row = base + l;
        size_t off = (size_t)row * DS + s;
        float dt = g_dt[off];
        float bt = g_bt[off];
        v = expf(-dt) * v + bt;
        float kf = (float)(Lseq - 1 - l);
        float denom = expm1f(-dt);
        if (denom > -1e-30f) denom = -1e-30f;
        float us = expf(-kf * dt) * v + bt * expm1f(-kf * dt) / denom;
        g_cat[afh_idx(row, EE + s,          KC_CAT)] = __float2half_rn(us);
        g_cat[afh_idx(row, EE + DS + s,     KC_CAT)] = __half(0.0f);
        g_cat[afh_idx(row, EE + 2 * DS + s, KC_CAT)] = __half(0.0f);
        g_cat[afh_idx(row, EE + 3 * DS + s, KC_CAT)] = __half(0.0f);
    }
}

// ======================= launch =============================================
extern "C" void kernel_launch(void* const* d_in, const int* in_sizes, int n_in,
                              void* d_out, int out_size) {
    const float* x      = (const float*)d_in[0];
    const float* ln_g   = (const float*)d_in[1];
    const float* ln_b   = (const float*)d_in[2];
    const float* W_in   = (const float*)d_in[3];
    const float* b_in   = (const float*)d_in[4];
    const float* W_conv = (const float*)d_in[5];
    const float* b_conv = (const float*)d_in[6];
    const float* W_xp   = (const float*)d_in[7];
    const float* b_xp   = (const float*)d_in[8];
    const float* W_dt   = (const float*)d_in[9];
    const float* b_dt   = (const float*)d_in[10];
    const float* W_us   = (const float*)d_in[11];
    const float* b_us   = (const float*)d_in[12];
    const float* W_out  = (const float*)d_in[13];
    const float* b_out  = (const float*)d_in[14];
    float* out = (float*)d_out;

    __half *xn, *xin, *cat, *winF, *wpsF, *xplF, *wolF, *comboF;
    float *xd, *bias32, *cbias;
    cudaGetSymbolAddress((void**)&xn,     g_xn);
    cudaGetSymbolAddress((void**)&xin,    g_xin);
    cudaGetSymbolAddress((void**)&cat,    g_cat);
    cudaGetSymbolAddress((void**)&xd,     g_xd);
    cudaGetSymbolAddress((void**)&bias32, g_bias32);
    cudaGetSymbolAddress((void**)&cbias,  g_cbias);
    cudaGetSymbolAddress((void**)&winF,   g_winF);
    cudaGetSymbolAddress((void**)&wpsF,   g_wpsF);
    cudaGetSymbolAddress((void**)&xplF,   g_xplF);
    cudaGetSymbolAddress((void**)&wolF,   g_wolF);
    cudaGetSymbolAddress((void**)&comboF, g_comboF);

    cudaFuncSetAttribute(gemm_f16_kernel<0>, cudaFuncAttributeMaxDynamicSharedMemorySize, GEMM_SMEM);
    cudaFuncSetAttribute(gemm_f16_kernel<1>, cudaFuncAttributeMaxDynamicSharedMemorySize, GEMM_SMEM);
    cudaFuncSetAttribute(gemm_f16_kernel<2>, cudaFuncAttributeMaxDynamicSharedMemorySize, GEMM_SMEM);

    // 1. merged weight prep
    prep_kernel<<<NB_CB, 256>>>(W_in, W_out, W_xp, W_dt, W_us,
                                b_xp, b_dt, b_us, b_out);

    // 2. W_combo rows [0,1536): xplF @ wolF^T + W_out_hi -> comboF (MODE 2)
    gemm_f16_kernel<2><<<dim3(DM/128, EE/128, 1), 256, GEMM_SMEM>>>(
        xplF, 48, wolF, nullptr, comboF, 0, DM, DM, W_out, 0);

    // 3. LayerNorm -> A_f
    ln_kernel<<<NROWS, 384>>>(x, ln_g, ln_b);

    // 4. in-proj: (8192x768)@(768x1536) -> xin fp16 row-major
    gemm_f16_kernel<1><<<dim3(EE/128, NROWS/128, 1), 256, GEMM_SMEM>>>(
        xn, 48, winF, b_in, xin, EE, EE, DM, nullptr, 0);

    // 5. conv + silu -> g_cat A_f (k-blocks 0..95)
    conv_silu_kernel<<<((NROWS/4) * (EE/2) + 255) / 256, 256>>>(b_conv, W_conv);

    // 6. small proj: (8192x1536)@(1536x32) -> xd, K split over grid.z=4
    gemm_f16_kernel<0><<<dim3(1, NROWS/128, XD_ZS), 256, GEMM_SMEM>>>(
        cat, KC_CAT, wpsF, bias32, xd, 32, 32, EE, nullptr,
        (size_t)NROWS * 32 * sizeof(float));

    // 7. fused prescan + scan + us -> g_cat k-blocks 96..99
    scan_kernel<<<Bsz * DS, 256>>>();

    // 8. final: (8192x1600)@(1600x768) + cbias -> out
    gemm_f16_kernel<0><<<dim3(DM/128, NROWS/128, 1), 256, GEMM_SMEM>>>(
        cat, KC_CAT, comboF, cbias, out, DM, DM, KCAT, nullptr, 0);
}

// round 14
// speedup vs baseline: 1.1952x; 1.1147x over previous
#include <cuda_runtime.h>
#include <cuda_fp16.h>
#include <cstdint>
#include <math.h>

#define Bsz 2
#define Lseq 4096
#define DM 768
#define DS 16
#define EE 1536
#define NROWS (Bsz*Lseq)      // 8192
#define KCAT 1600             // 1536 (xact) + 16 (us) + 48 (zero pad)
#define KC_CAT 100            // KCAT/16
#define LN_EPS 1e-5f
#define XD_ZS 4               // K-split factor for small proj

#define STAGE_BYTES 32768     // A tile 16KB + B tile 16KB (K-chunk 64, fp16)
#define GEMM_SMEM (3 * STAGE_BYTES)

// merged prep+ln kernel block-region boundaries (384 threads/block)
#define PB_WIN  3072          // EE*DM/384
#define PB_WOL  (PB_WIN + 1536)
#define PB_XPL  (PB_WOL + 3072)
#define PB_WPS  (PB_XPL + 512)
#define PB_WUS2 (PB_WPS + 24)
#define PB_CB   (PB_WUS2 + 2)
#define PB_TOTAL (PB_CB + NROWS)

// ======================= small PTX helpers ==================================
__device__ __forceinline__ uint32_t smem_u32(const void* p) {
    uint32_t a;
    asm("{ .reg .u64 t; cvta.to.shared.u64 t, %1; cvt.u32.u64 %0, t; }"
        : "=r"(a) : "l"(p));
    return a;
}
__device__ __forceinline__ void cp_async16(uint32_t dst, const void* src) {
    asm volatile("cp.async.cg.shared.global [%0], [%1], 16;"
                 :: "r"(dst), "l"(src) : "memory");
}
__device__ __forceinline__ void cp_commit() {
    asm volatile("cp.async.commit_group;" ::: "memory");
}
template<int N> __device__ __forceinline__ void cp_wait() {
    asm volatile("cp.async.wait_group %0;" :: "n"(N) : "memory");
}
__device__ __forceinline__ void mma_f16(float* c, const uint32_t* a, const uint32_t* b) {
    asm volatile("mma.sync.aligned.m16n8k16.row.col.f32.f16.f16.f32 "
        "{%0,%1,%2,%3}, {%4,%5,%6,%7}, {%8,%9}, {%0,%1,%2,%3};"
        : "+f"(c[0]), "+f"(c[1]), "+f"(c[2]), "+f"(c[3])
        : "r"(a[0]), "r"(a[1]), "r"(a[2]), "r"(a[3]), "r"(b[0]), "r"(b[1]));
}

// ---- fp16 fragment-native layouts (half-element index), R10 versions --------
__device__ __forceinline__ size_t afh_idx(int r, int k, int KC16) {
    size_t blk = (size_t)((r >> 4) * KC16 + (k >> 4));
    int b32 = (r & 7) * 16 + ((k >> 1) & 3) * 4 + ((r >> 3) & 1) + 2 * ((k >> 3) & 1);
    return blk * 256 + b32 * 2 + (k & 1);
}
__device__ __forceinline__ void afh_inv(int idx, int KC16, int& r, int& k) {
    int blk = idx >> 8;
    int b32 = (idx & 255) >> 1, h = idx & 1;
    r = (blk / KC16) * 16 + ((b32 & 1) << 3) + (b32 >> 4);
    k = ((blk % KC16) << 4) | (((b32 >> 1) & 1) << 3) | (((b32 >> 2) & 3) << 1) | h;
}
__device__ __forceinline__ size_t bfh_idx(int n, int k, int KC16) {
    size_t blk = (size_t)((n >> 3) * KC16 + (k >> 4));
    int b32 = (n & 7) * 8 + ((k >> 1) & 3) * 2 + ((k >> 3) & 1);
    return blk * 128 + b32 * 2 + (k & 1);
}
__device__ __forceinline__ void bfh_inv(int idx, int KC16, int& n, int& k) {
    int blk = idx >> 7;
    int b32 = (idx & 127) >> 1, h = idx & 1;
    n = (blk / KC16) * 8 + (b32 >> 3);
    k = ((blk % KC16) << 4) | ((b32 & 1) << 3) | (((b32 >> 1) & 3) << 1) | h;
}

// ======================= scratch ============================================
__device__ __align__(256) __half g_xn    [NROWS * DM];     // A_f (K=768)
__device__ __align__(256) __half g_xin   [NROWS * EE];     // fp16 row-major
__device__ __align__(256) __half g_cat   [NROWS * KCAT];   // A_f: xact|us|0
__device__ __align__(256) float  g_xd    [XD_ZS * NROWS * 32]; // ds|dt_raw partials
__device__ float g_dt [NROWS * DS];
__device__ float g_bt [NROWS * DS];
__device__ float g_bias32[32];
__device__ float g_cbias [DM];
__device__ __align__(256) __half g_winF  [EE * DM];        // B_f: N=1536, K=768
__device__ __align__(256) __half g_wpsF  [128 * EE];       // B_f: N=128(pad), K=1536
__device__ __align__(256) __half g_xplF  [EE * DM];        // A_f: W_xp_low (M=1536,K=768)
__device__ __align__(256) __half g_wolF  [DM * DM];        // B_f: W_out_low (N=768,K=768)
__device__ __align__(256) __half g_comboF[(DM/8) * KC_CAT * 128]; // B_f: N=768, K=1600

// ======================= fp16 mma.sync GEMM (R10 champion) ==================
// Block 128x128, 8 warps (wm=wid>>1 32 rows, wn=wid&1 64 cols), K-chunk 64,
// 3-stage cp.async.
// MODE 0: float row-major out (+bias)   MODE 1: half row-major out (+bias)
// MODE 2: half out in bfh layout (k=row, n=col, KC16=KC_CAT), += addW row>=768
// grid.z>1: K split across z; bias only z==0; out += z*zstride bytes.
template<int MODE>
__global__ __launch_bounds__(256, 2) void gemm_f16_kernel(
    const __half* __restrict__ Af, int kc16s,
    const __half* __restrict__ Bf,
    const float* __restrict__ bias, void* __restrict__ Cv,
    int ldc, int Ndim, int K, const float* __restrict__ addW,
    size_t zstride)
{
    extern __shared__ __align__(16) char sm[];
    const int tid = threadIdx.x;
    const int wid = tid >> 5, lane = tid & 31;
    const int wm = wid >> 1, wn = wid & 1;
    const int g = lane >> 2, tg = lane & 3;
    const int KC16 = K >> 4;
    const int NCz = (K >> 6) / gridDim.z;
    const int c0 = blockIdx.z * NCz;
    const int mp0 = blockIdx.y * 8;
    const int ng0 = blockIdx.x * 16;
    const int m0 = blockIdx.y * 128, n0 = blockIdx.x * 128;
    const uint32_t smb = smem_u32(sm);

    auto load_chunk = [&](int i) {
        const int c = c0 + i;
        const uint32_t st = (uint32_t)(i % 3) * STAGE_BYTES;
        #pragma unroll
        for (int j = 0; j < 4; j++) {
            int L = tid + 256 * j;
            int pp = L >> 7, qq = (L >> 5) & 3, ll = L & 31;
            const __half* src = Af + ((size_t)(mp0 + pp) * kc16s + 4 * c + qq) * 256 + ll * 8;
            cp_async16(smb + st + (uint32_t)((pp * 4 + qq) * 512 + ll * 16), src);
        }
        #pragma unroll
        for (int j = 0; j < 4; j++) {
            int L = tid + 256 * j;
            int ng = L >> 6, qq = (L >> 4) & 3, ll = L & 15;
            const __half* src = Bf + ((size_t)(ng0 + ng) * KC16 + 4 * c + qq) * 128 + ll * 8;
            cp_async16(smb + st + 16384u + (uint32_t)((ng * 4 + qq) * 256 + ll * 16), src);
        }
        cp_commit();
    };

    float acc[2][8][4];
    #pragma unroll
    for (int mi = 0; mi < 2; mi++)
        #pragma unroll
        for (int ni = 0; ni < 8; ni++)
            #pragma unroll
            for (int q = 0; q < 4; q++) acc[mi][ni][q] = 0.0f;

    load_chunk(0); load_chunk(1);

    const char* stA_w = sm + wm * 4096 + g * 64 + tg * 16;
    const char* stB_w = sm + 16384 + wn * 8192 + g * 32 + tg * 8;

    for (int i = 0; i < NCz; i++) {
        cp_wait<1>();
        __syncthreads();
        if (i + 2 < NCz) load_chunk(i + 2); else cp_commit();

        const char* stA = stA_w + (i % 3) * STAGE_BYTES;
        const char* stB = stB_w + (i % 3) * STAGE_BYTES;

        #pragma unroll
        for (int kb = 0; kb < 4; kb++) {
            uint4 a0 = *(const uint4*)(stA + kb * 512);
            uint4 a1 = *(const uint4*)(stA + 2048 + kb * 512);
            uint2 bq[8];
            #pragma unroll
            for (int ni = 0; ni < 8; ni++)
                bq[ni] = *(const uint2*)(stB + ni * 1024 + kb * 256);
            #pragma unroll
            for (int ni = 0; ni < 8; ni++) {
                mma_f16(acc[0][ni], (const uint32_t*)&a0, (const uint32_t*)&bq[ni]);
                mma_f16(acc[1][ni], (const uint32_t*)&a1, (const uint32_t*)&bq[ni]);
            }
        }
    }

    if (MODE == 2) {
        __half* Cc = (__half*)Cv;
        #pragma unroll
        for (int mi = 0; mi < 2; mi++)
            #pragma unroll
            for (int ni = 0; ni < 8; ni++)
                #pragma unroll
                for (int q = 0; q < 4; q++) {
                    int row = m0 + wm * 32 + mi * 16 + g + ((q >> 1) << 3);
                    int col = n0 + wn * 64 + ni * 8 + tg * 2 + (q & 1);
                    float v = acc[mi][ni][q];
                    if (row >= DM) v += addW[(size_t)row * DM + col];
                    Cc[bfh_idx(col, row, KC_CAT)] = __float2half_rn(v);
                }
    } else {
        const bool ub = (blockIdx.z == 0);
        char* Cz = (char*)Cv + (size_t)blockIdx.z * zstride;
        #pragma unroll
        for (int mi = 0; mi < 2; mi++) {
            const int row = m0 + wm * 32 + mi * 16 + g;
            #pragma unroll
            for (int ni = 0; ni < 8; ni++) {
                const int col = n0 + wn * 64 + ni * 8 + tg * 2;
                if (col < Ndim) {
                    float bx = ub ? bias[col] : 0.0f;
                    float by = ub ? bias[col + 1] : 0.0f;
                    float v00 = acc[mi][ni][0] + bx, v01 = acc[mi][ni][1] + by;
                    float v10 = acc[mi][ni][2] + bx, v11 = acc[mi][ni][3] + by;
                    if (MODE == 1) {
                        __half* c0 = (__half*)Cz + (size_t)row * ldc;
                        __half* c1 = (__half*)Cz + (size_t)(row + 8) * ldc;
                        *(__half2*)(c0 + col) = __floats2half2_rn(v00, v01);
                        *(__half2*)(c1 + col) = __floats2half2_rn(v10, v11);
                    } else {
                        float* c0 = (float*)Cz + (size_t)row * ldc;
                        float* c1 = (float*)Cz + (size_t)(row + 8) * ldc;
                        *(float2*)(c0 + col) = make_float2(v00, v01);
                        *(float2*)(c1 + col) = make_float2(v10, v11);
                    }
                }
            }
        }
    }
}

// ======================= merged prep + LayerNorm kernel =====================
// 384 threads. Blocks [0, PB_CB): weight prep regions. Blocks [PB_CB, PB_TOTAL):
// LayerNorm rows (one row per block, float2 loads, half2 stores into A_f).
__global__ __launch_bounds__(384) void prep_ln_kernel(
    const float* __restrict__ W_in,
    const float* __restrict__ W_out,
    const float* __restrict__ W_xp,
    const float* __restrict__ W_dt,
    const float* __restrict__ W_us,
    const float* __restrict__ b_xp,
    const float* __restrict__ b_dt,
    const float* __restrict__ b_us,
    const float* __restrict__ b_out,
    const float* __restrict__ x,
    const float* __restrict__ ln_g,
    const float* __restrict__ ln_b)
{
    __shared__ float sh[4096];
    const int blk = blockIdx.x;
    const int tid = threadIdx.x;

    if (blk >= PB_CB) {
        // ---------------- LayerNorm row ----------------
        int row = blk - PB_CB;
        const float2* xr = (const float2*)(x + (size_t)row * DM);
        float2 v = xr[tid];
        if (tid < 128) sh[384 + tid] = 0.0f;
        sh[tid] = v.x + v.y;
        __syncthreads();
        for (int off = 256; off > 0; off >>= 1) {
            if (tid < off) sh[tid] += sh[tid + off];
            __syncthreads();
        }
        float mu = sh[0] * (1.0f / DM);
        __syncthreads();
        float dx = v.x - mu, dy = v.y - mu;
        sh[tid] = dx * dx + dy * dy;
        __syncthreads();
        for (int off = 256; off > 0; off >>= 1) {
            if (tid < off) sh[tid] += sh[tid + off];
            __syncthreads();
        }
        float rstd = rsqrtf(sh[0] * (1.0f / DM) + LN_EPS);
        float2 gg = ((const float2*)ln_g)[tid];
        float2 bb = ((const float2*)ln_b)[tid];
        float h0 = dx * rstd * gg.x + bb.x;
        float h1 = dy * rstd * gg.y + bb.y;
        *(__half2*)(g_xn + afh_idx(row, 2 * tid, 48)) = __floats2half2_rn(h0, h1);
        return;
    }

    if (blk < PB_WIN) {
        int idx = blk * 384 + tid;
        int n, k; bfh_inv(idx, 48, n, k);
        g_winF[idx] = __float2half_rn(W_in[(size_t)k * EE + n]);
    } else if (blk < PB_WOL) {
        int idx = (blk - PB_WIN) * 384 + tid;
        int n, k; bfh_inv(idx, 48, n, k);
        g_wolF[idx] = __float2half_rn(W_out[(size_t)k * DM + n]);
    } else if (blk < PB_XPL) {
        int idx = (blk - PB_WOL) * 384 + tid;
        int r, k; afh_inv(idx, 48, r, k);
        g_xplF[idx] = __float2half_rn(W_xp[(size_t)r * (DM + DS) + k]);
    } else if (blk < PB_WPS) {
        int idx = (blk - PB_XPL) * 384 + tid;
        int n, k; bfh_inv(idx, 96, n, k);
        float v = (n < DS)     ? W_xp[(size_t)k * (DM + DS) + DM + n]
                : (n < 2 * DS) ? W_dt[(size_t)k * DS + (n - DS)]
                : 0.0f;
        g_wpsF[idx] = __float2half_rn(v);
        if (blk == PB_XPL && tid < 32)
            g_bias32[tid] = (tid < DS) ? b_xp[DM + tid] : b_dt[tid - DS];
    } else if (blk < PB_WUS2) {
        // W_us2 = W_us(16x768) @ W_out_low(768x768): 24 blocks x 32 n each.
        // Only first 256 threads participate (8 j-chunks x 32 lanes).
        float (*red)[16][32] = (float (*)[16][32])sh;
        int bb = blk - PB_WPS;
        if (tid < 256) {
            int n = bb * 32 + (tid & 31);
            int chunk = tid >> 5;
            float acc[16];
            #pragma unroll
            for (int s = 0; s < 16; s++) acc[s] = 0.0f;
            for (int j = chunk * 96; j < chunk * 96 + 96; j++) {
                float wo = W_out[(size_t)j * DM + n];
                #pragma unroll
                for (int s = 0; s < 16; s++)
                    acc[s] = fmaf(W_us[(size_t)s * DM + j], wo, acc[s]);
            }
            #pragma unroll
            for (int s = 0; s < 16; s++) red[chunk][s][tid & 31] = acc[s];
        }
        __syncthreads();
        for (int o = tid; o < 512; o += 384) {
            int s = o >> 5, ln = o & 31;
            float t = 0.0f;
            #pragma unroll
            for (int c = 0; c < 8; c++) t += red[c][s][ln];
            int nn = bb * 32 + ln;
            g_comboF[bfh_idx(nn, EE + s,          KC_CAT)] = __float2half_rn(t);
            g_comboF[bfh_idx(nn, EE + DS + s,     KC_CAT)] = __half(0.0f);
            g_comboF[bfh_idx(nn, EE + 2 * DS + s, KC_CAT)] = __half(0.0f);
            g_comboF[bfh_idx(nn, EE + 3 * DS + s, KC_CAT)] = __half(0.0f);
        }
    } else {
        int n = (blk - PB_WUS2) * 384 + tid;
        if (n < DM) {
            float acc = b_out[n];
            for (int j = 0; j < DM; j++)
                acc = fmaf(b_xp[j] + b_us[j], W_out[(size_t)j * DM + n], acc);
            g_cbias[n] = acc;
        }
    }
}

// ======================= depthwise conv (k=4) + SiLU, channel pairs =========
__global__ void conv_silu_kernel(const float* __restrict__ b_conv,
                                 const float* __restrict__ W_conv) {
    int idx = blockIdx.x * blockDim.x + threadIdx.x;
    if (idx >= (NROWS / 4) * (EE / 2)) return;
    int ep = idx % (EE / 2);
    int e0 = ep * 2;
    int r0 = (idx / (EE / 2)) * 4;
    int l0 = r0 % Lseq;
    const __half2* xin2 = (const __half2*)g_xin;

    float2 xa[7];
    #pragma unroll
    for (int j = 0; j < 3; j++) {
        if (l0 >= 3 - j) xa[j] = __half22float2(xin2[(size_t)(r0 - 3 + j) * (EE/2) + ep]);
        else             xa[j] = make_float2(0.f, 0.f);
    }
    #pragma unroll
    for (int j = 3; j < 7; j++)
        xa[j] = __half22float2(xin2[(size_t)(r0 - 3 + j) * (EE/2) + ep]);

    float4 wA = *(const float4*)(W_conv + e0 * 4);
    float4 wB = *(const float4*)(W_conv + e0 * 4 + 4);
    float bc0 = b_conv[e0], bc1 = b_conv[e0 + 1];

    #pragma unroll
    for (int i = 0; i < 4; i++) {
        float sx = bc0 + xa[i].x * wA.x + xa[i+1].x * wA.y + xa[i+2].x * wA.z + xa[i+3].x * wA.w;
        float sy = bc1 + xa[i].y * wB.x + xa[i+1].y * wB.y + xa[i+2].y * wB.z + xa[i+3].y * wB.w;
        float ax = sx / (1.0f + expf(-sx));
        float ay = sy / (1.0f + expf(-sy));
        *(__half2*)(g_cat + afh_idx(r0 + i, e0, KC_CAT)) = __floats2half2_rn(ax, ay);
    }
}

// ======================= fused prescan + scan + us ==========================
__global__ __launch_bounds__(256) void scan_kernel() {
    int chan = blockIdx.x;
    int bb = chan / DS, s = chan % DS;
    int t = threadIdx.x;
    __shared__ float sA[256], sB[256];
    float A = 1.0f, Bl = 0.0f;
    int base = bb * Lseq;
    #pragma unroll 4
    for (int i = 0; i < 16; i++) {
        size_t rofs = (size_t)(base + t * 16 + i);
        float ds = 0.0f, dtraw = 0.0f;
        #pragma unroll
        for (int z = 0; z < XD_ZS; z++) {
            ds    += g_xd[(size_t)z * NROWS * 32 + rofs * 32 + s];
            dtraw += g_xd[(size_t)z * NROWS * 32 + rofs * 32 + 16 + s];
        }
        float dt = fmaxf(dtraw, 0.0f) + log1pf(expf(-fabsf(dtraw)));
        float bt = ds * expf(-0.5f * dt);
        g_dt[rofs * DS + s] = dt;
        g_bt[rofs * DS + s] = bt;
        float a = expf(-dt);
        Bl = a * Bl + bt;
        A = a * A;
    }
    sA[t] = A; sB[t] = Bl;
    __syncthreads();
    for (int offp = 1; offp < 256; offp <<= 1) {
        float pA = 0.f, pB = 0.f;
        bool has = (t >= offp);
        if (has) { pA = sA[t - offp]; pB = sB[t - offp]; }
        __syncthreads();
        if (has) { sB[t] = sA[t] * pB + sB[t]; sA[t] = sA[t] * pA; }
        __syncthreads();
    }
    float v = (t == 0) ? 0.0f : sB[t - 1];
    for (int i = 0; i < 16; i++) {
        int l = t * 16 + i;
        int row = base + l;
        size_t off = (size_t)row * DS + s;
        float dt = g_dt[off];
        float bt = g_bt[off];
        v = expf(-dt) * v + bt;
        float kf = (float)(Lseq - 1 - l);
        float denom = expm1f(-dt);
        if (denom > -1e-30f) denom = -1e-30f;
        float us = expf(-kf * dt) * v + bt * expm1f(-kf * dt) / denom;
        g_cat[afh_idx(row, EE + s,          KC_CAT)] = __float2half_rn(us);
        g_cat[afh_idx(row, EE + DS + s,     KC_CAT)] = __half(0.0f);
        g_cat[afh_idx(row, EE + 2 * DS + s, KC_CAT)] = __half(0.0f);
        g_cat[afh_idx(row, EE + 3 * DS + s, KC_CAT)] = __half(0.0f);
    }
}

// ======================= launch =============================================
extern "C" void kernel_launch(void* const* d_in, const int* in_sizes, int n_in,
                              void* d_out, int out_size) {
    const float* x      = (const float*)d_in[0];
    const float* ln_g   = (const float*)d_in[1];
    const float* ln_b   = (const float*)d_in[2];
    const float* W_in   = (const float*)d_in[3];
    const float* b_in   = (const float*)d_in[4];
    const float* W_conv = (const float*)d_in[5];
    const float* b_conv = (const float*)d_in[6];
    const float* W_xp   = (const float*)d_in[7];
    const float* b_xp   = (const float*)d_in[8];
    const float* W_dt   = (const float*)d_in[9];
    const float* b_dt   = (const float*)d_in[10];
    const float* W_us   = (const float*)d_in[11];
    const float* b_us   = (const float*)d_in[12];
    const float* W_out  = (const float*)d_in[13];
    const float* b_out  = (const float*)d_in[14];
    float* out = (float*)d_out;

    __half *xn, *xin, *cat, *winF, *wpsF, *xplF, *wolF, *comboF;
    float *xd, *bias32, *cbias;
    cudaGetSymbolAddress((void**)&xn,     g_xn);
    cudaGetSymbolAddress((void**)&xin,    g_xin);
    cudaGetSymbolAddress((void**)&cat,    g_cat);
    cudaGetSymbolAddress((void**)&xd,     g_xd);
    cudaGetSymbolAddress((void**)&bias32, g_bias32);
    cudaGetSymbolAddress((void**)&cbias,  g_cbias);
    cudaGetSymbolAddress((void**)&winF,   g_winF);
    cudaGetSymbolAddress((void**)&wpsF,   g_wpsF);
    cudaGetSymbolAddress((void**)&xplF,   g_xplF);
    cudaGetSymbolAddress((void**)&wolF,   g_wolF);
    cudaGetSymbolAddress((void**)&comboF, g_comboF);

    cudaFuncSetAttribute(gemm_f16_kernel<0>, cudaFuncAttributeMaxDynamicSharedMemorySize, GEMM_SMEM);
    cudaFuncSetAttribute(gemm_f16_kernel<1>, cudaFuncAttributeMaxDynamicSharedMemorySize, GEMM_SMEM);
    cudaFuncSetAttribute(gemm_f16_kernel<2>, cudaFuncAttributeMaxDynamicSharedMemorySize, GEMM_SMEM);

    // 1. merged weight prep + LayerNorm
    prep_ln_kernel<<<PB_TOTAL, 384>>>(W_in, W_out, W_xp, W_dt, W_us,
                                      b_xp, b_dt, b_us, b_out,
                                      x, ln_g, ln_b);

    // 2. W_combo rows [0,1536): xplF @ wolF^T + W_out_hi -> comboF (MODE 2)
    gemm_f16_kernel<2><<<dim3(DM/128, EE/128, 1), 256, GEMM_SMEM>>>(
        xplF, 48, wolF, nullptr, comboF, 0, DM, DM, W_out, 0);

    // 3. in-proj: (8192x768)@(768x1536) -> xin fp16 row-major
    gemm_f16_kernel<1><<<dim3(EE/128, NROWS/128, 1), 256, GEMM_SMEM>>>(
        xn, 48, winF, b_in, xin, EE, EE, DM, nullptr, 0);

    // 4. conv + silu -> g_cat A_f (k-blocks 0..95)
    conv_silu_kernel<<<((NROWS/4) * (EE/2) + 255) / 256, 256>>>(b_conv, W_conv);

    // 5. small proj: (8192x1536)@(1536x32) -> xd, K split over grid.z=4
    gemm_f16_kernel<0><<<dim3(1, NROWS/128, XD_ZS), 256, GEMM_SMEM>>>(
        cat, KC_CAT, wpsF, bias32, xd, 32, 32, EE, nullptr,
        (size_t)NROWS * 32 * sizeof(float));

    // 6. fused prescan + scan + us -> g_cat k-blocks 96..99
    scan_kernel<<<Bsz * DS, 256>>>();

    // 7. final: (8192x1600)@(1600x768) + cbias -> out
    gemm_f16_kernel<0><<<dim3(DM/128, NROWS/128, 1), 256, GEMM_SMEM>>>(
        cat, KC_CAT, comboF, cbias, out, DM, DM, KCAT, nullptr, 0);
}

// round 15
// speedup vs baseline: 1.2041x; 1.0074x over previous
#include <cuda_runtime.h>
#include <cuda_fp16.h>
#include <cstdint>
#include <math.h>

#define Bsz 2
#define Lseq 4096
#define DM 768
#define DS 16
#define EE 1536
#define NROWS (Bsz*Lseq)      // 8192
#define KCAT 1600             // 1536 (xact) + 16 (us) + 48 (zero pad)
#define KC_CAT 100            // KCAT/16
#define LN_EPS 1e-5f
#define XD_ZS 4               // K-split factor for small proj

#define STAGE_BYTES 32768     // A tile 16KB + B tile 16KB (K-chunk 64, fp16)
#define GEMM_SMEM (3 * STAGE_BYTES)

// merged prep+ln kernel block-region boundaries (384 threads/block)
#define PB_WIN  3072          // EE*DM/384
#define PB_WOL  (PB_WIN + 1536)
#define PB_XPL  (PB_WOL + 3072)
#define PB_WPS  (PB_XPL + 512)
#define PB_WUS2 (PB_WPS + 24)
#define PB_CB   (PB_WUS2 + 2)
#define PB_TOTAL (PB_CB + NROWS)

// ======================= small PTX helpers ==================================
__device__ __forceinline__ uint32_t smem_u32(const void* p) {
    uint32_t a;
    asm("{ .reg .u64 t; cvta.to.shared.u64 t, %1; cvt.u32.u64 %0, t; }"
        : "=r"(a) : "l"(p));
    return a;
}
__device__ __forceinline__ void cp_async16(uint32_t dst, const void* src) {
    asm volatile("cp.async.cg.shared.global [%0], [%1], 16;"
                 :: "r"(dst), "l"(src) : "memory");
}
__device__ __forceinline__ void cp_commit() {
    asm volatile("cp.async.commit_group;" ::: "memory");
}
template<int N> __device__ __forceinline__ void cp_wait() {
    asm volatile("cp.async.wait_group %0;" :: "n"(N) : "memory");
}
__device__ __forceinline__ void mma_f16(float* c, const uint32_t* a, const uint32_t* b) {
    asm volatile("mma.sync.aligned.m16n8k16.row.col.f32.f16.f16.f32 "
        "{%0,%1,%2,%3}, {%4,%5,%6,%7}, {%8,%9}, {%0,%1,%2,%3};"
        : "+f"(c[0]), "+f"(c[1]), "+f"(c[2]), "+f"(c[3])
        : "r"(a[0]), "r"(a[1]), "r"(a[2]), "r"(a[3]), "r"(b[0]), "r"(b[1]));
}

// ---- fp16 fragment-native layouts (half-element index) ----------------------
__device__ __forceinline__ size_t afh_idx(int r, int k, int KC16) {
    size_t blk = (size_t)((r >> 4) * KC16 + (k >> 4));
    int b32 = (r & 7) * 16 + ((k >> 1) & 3) * 4 + ((r >> 3) & 1) + 2 * ((k >> 3) & 1);
    return blk * 256 + b32 * 2 + (k & 1);
}
__device__ __forceinline__ void afh_inv(int idx, int KC16, int& r, int& k) {
    int blk = idx >> 8;
    int b32 = (idx & 255) >> 1, h = idx & 1;
    r = (blk / KC16) * 16 + ((b32 & 1) << 3) + (b32 >> 4);
    k = ((blk % KC16) << 4) | (((b32 >> 1) & 1) << 3) | (((b32 >> 2) & 3) << 1) | h;
}
__device__ __forceinline__ size_t bfh_idx(int n, int k, int KC16) {
    size_t blk = (size_t)((n >> 3) * KC16 + (k >> 4));
    int b32 = (n & 7) * 8 + ((k >> 1) & 3) * 2 + ((k >> 3) & 1);
    return blk * 128 + b32 * 2 + (k & 1);
}
__device__ __forceinline__ void bfh_inv(int idx, int KC16, int& n, int& k) {
    int blk = idx >> 7;
    int b32 = (idx & 127) >> 1, h = idx & 1;
    n = (blk / KC16) * 8 + (b32 >> 3);
    k = ((blk % KC16) << 4) | ((b32 & 1) << 3) | (((b32 >> 1) & 3) << 1) | h;
}

// ======================= scratch ============================================
__device__ __align__(256) __half g_xn    [NROWS * DM];     // A_f (K=768)
__device__ __align__(256) __half g_xin   [NROWS * EE];     // fp16 row-major
__device__ __align__(256) __half g_cat   [NROWS * KCAT];   // A_f: xact|us|0
__device__ __align__(256) float  g_xd    [XD_ZS * NROWS * 32]; // ds|dt_raw partials
__device__ float g_dt [NROWS * DS];
__device__ float g_bt [NROWS * DS];
__device__ float g_bias32[32];
__device__ float g_cbias [DM];
__device__ __align__(256) __half g_winF  [EE * DM];        // B_f: N=1536, K=768
__device__ __align__(256) __half g_wpsF  [128 * EE];       // B_f: N=128(pad), K=1536
__device__ __align__(256) __half g_xplF  [EE * DM];        // A_f: W_xp_low (M=1536,K=768)
__device__ __align__(256) __half g_wolF  [DM * DM];        // B_f: W_out_low (N=768,K=768)
__device__ __align__(256) __half g_comboF[(DM/8) * KC_CAT * 128]; // B_f: N=768, K=1600

// ======================= fp16 mma.sync GEMM (R10 champion) ==================
template<int MODE>
__global__ __launch_bounds__(256, 2) void gemm_f16_kernel(
    const __half* __restrict__ Af, int kc16s,
    const __half* __restrict__ Bf,
    const float* __restrict__ bias, void* __restrict__ Cv,
    int ldc, int Ndim, int K, const float* __restrict__ addW,
    size_t zstride)
{
    extern __shared__ __align__(16) char sm[];
    const int tid = threadIdx.x;
    const int wid = tid >> 5, lane = tid & 31;
    const int wm = wid >> 1, wn = wid & 1;
    const int g = lane >> 2, tg = lane & 3;
    const int KC16 = K >> 4;
    const int NCz = (K >> 6) / gridDim.z;
    const int c0 = blockIdx.z * NCz;
    const int mp0 = blockIdx.y * 8;
    const int ng0 = blockIdx.x * 16;
    const int m0 = blockIdx.y * 128, n0 = blockIdx.x * 128;
    const uint32_t smb = smem_u32(sm);

    auto load_chunk = [&](int i) {
        const int c = c0 + i;
        const uint32_t st = (uint32_t)(i % 3) * STAGE_BYTES;
        #pragma unroll
        for (int j = 0; j < 4; j++) {
            int L = tid + 256 * j;
            int pp = L >> 7, qq = (L >> 5) & 3, ll = L & 31;
            const __half* src = Af + ((size_t)(mp0 + pp) * kc16s + 4 * c + qq) * 256 + ll * 8;
            cp_async16(smb + st + (uint32_t)((pp * 4 + qq) * 512 + ll * 16), src);
        }
        #pragma unroll
        for (int j = 0; j < 4; j++) {
            int L = tid + 256 * j;
            int ng = L >> 6, qq = (L >> 4) & 3, ll = L & 15;
            const __half* src = Bf + ((size_t)(ng0 + ng) * KC16 + 4 * c + qq) * 128 + ll * 8;
            cp_async16(smb + st + 16384u + (uint32_t)((ng * 4 + qq) * 256 + ll * 16), src);
        }
        cp_commit();
    };

    float acc[2][8][4];
    #pragma unroll
    for (int mi = 0; mi < 2; mi++)
        #pragma unroll
        for (int ni = 0; ni < 8; ni++)
            #pragma unroll
            for (int q = 0; q < 4; q++) acc[mi][ni][q] = 0.0f;

    load_chunk(0); load_chunk(1);

    const char* stA_w = sm + wm * 4096 + g * 64 + tg * 16;
    const char* stB_w = sm + 16384 + wn * 8192 + g * 32 + tg * 8;

    for (int i = 0; i < NCz; i++) {
        cp_wait<1>();
        __syncthreads();
        if (i + 2 < NCz) load_chunk(i + 2); else cp_commit();

        const char* stA = stA_w + (i % 3) * STAGE_BYTES;
        const char* stB = stB_w + (i % 3) * STAGE_BYTES;

        #pragma unroll
        for (int kb = 0; kb < 4; kb++) {
            uint4 a0 = *(const uint4*)(stA + kb * 512);
            uint4 a1 = *(const uint4*)(stA + 2048 + kb * 512);
            uint2 bq[8];
            #pragma unroll
            for (int ni = 0; ni < 8; ni++)
                bq[ni] = *(const uint2*)(stB + ni * 1024 + kb * 256);
            #pragma unroll
            for (int ni = 0; ni < 8; ni++) {
                mma_f16(acc[0][ni], (const uint32_t*)&a0, (const uint32_t*)&bq[ni]);
                mma_f16(acc[1][ni], (const uint32_t*)&a1, (const uint32_t*)&bq[ni]);
            }
        }
    }

    if (MODE == 2) {
        __half* Cc = (__half*)Cv;
        #pragma unroll
        for (int mi = 0; mi < 2; mi++)
            #pragma unroll
            for (int ni = 0; ni < 8; ni++)
                #pragma unroll
                for (int q = 0; q < 4; q++) {
                    int row = m0 + wm * 32 + mi * 16 + g + ((q >> 1) << 3);
                    int col = n0 + wn * 64 + ni * 8 + tg * 2 + (q & 1);
                    float v = acc[mi][ni][q];
                    if (row >= DM) v += addW[(size_t)row * DM + col];
                    Cc[bfh_idx(col, row, KC_CAT)] = __float2half_rn(v);
                }
    } else {
        const bool ub = (blockIdx.z == 0);
        char* Cz = (char*)Cv + (size_t)blockIdx.z * zstride;
        #pragma unroll
        for (int mi = 0; mi < 2; mi++) {
            const int row = m0 + wm * 32 + mi * 16 + g;
            #pragma unroll
            for (int ni = 0; ni < 8; ni++) {
                const int col = n0 + wn * 64 + ni * 8 + tg * 2;
                if (col < Ndim) {
                    float bx = ub ? bias[col] : 0.0f;
                    float by = ub ? bias[col + 1] : 0.0f;
                    float v00 = acc[mi][ni][0] + bx, v01 = acc[mi][ni][1] + by;
                    float v10 = acc[mi][ni][2] + bx, v11 = acc[mi][ni][3] + by;
                    if (MODE == 1) {
                        __half* c0 = (__half*)Cz + (size_t)row * ldc;
                        __half* c1 = (__half*)Cz + (size_t)(row + 8) * ldc;
                        *(__half2*)(c0 + col) = __floats2half2_rn(v00, v01);
                        *(__half2*)(c1 + col) = __floats2half2_rn(v10, v11);
                    } else {
                        float* c0 = (float*)Cz + (size_t)row * ldc;
                        float* c1 = (float*)Cz + (size_t)(row + 8) * ldc;
                        *(float2*)(c0 + col) = make_float2(v00, v01);
                        *(float2*)(c1 + col) = make_float2(v10, v11);
                    }
                }
            }
        }
    }
}

// ======================= merged prep + LayerNorm kernel =====================
__global__ __launch_bounds__(384) void prep_ln_kernel(
    const float* __restrict__ W_in,
    const float* __restrict__ W_out,
    const float* __restrict__ W_xp,
    const float* __restrict__ W_dt,
    const float* __restrict__ W_us,
    const float* __restrict__ b_xp,
    const float* __restrict__ b_dt,
    const float* __restrict__ b_us,
    const float* __restrict__ b_out,
    const float* __restrict__ x,
    const float* __restrict__ ln_g,
    const float* __restrict__ ln_b)
{
    __shared__ float sh[4096];
    const int blk = blockIdx.x;
    const int tid = threadIdx.x;

    if (blk >= PB_CB) {
        int row = blk - PB_CB;
        const float2* xr = (const float2*)(x + (size_t)row * DM);
        float2 v = xr[tid];
        if (tid < 128) sh[384 + tid] = 0.0f;
        sh[tid] = v.x + v.y;
        __syncthreads();
        for (int off = 256; off > 0; off >>= 1) {
            if (tid < off) sh[tid] += sh[tid + off];
            __syncthreads();
        }
        float mu = sh[0] * (1.0f / DM);
        __syncthreads();
        float dx = v.x - mu, dy = v.y - mu;
        sh[tid] = dx * dx + dy * dy;
        __syncthreads();
        for (int off = 256; off > 0; off >>= 1) {
            if (tid < off) sh[tid] += sh[tid + off];
            __syncthreads();
        }
        float rstd = rsqrtf(sh[0] * (1.0f / DM) + LN_EPS);
        float2 gg = ((const float2*)ln_g)[tid];
        float2 bb = ((const float2*)ln_b)[tid];
        float h0 = dx * rstd * gg.x + bb.x;
        float h1 = dy * rstd * gg.y + bb.y;
        *(__half2*)(g_xn + afh_idx(row, 2 * tid, 48)) = __floats2half2_rn(h0, h1);
        return;
    }

    if (blk < PB_WIN) {
        int idx = blk * 384 + tid;
        int n, k; bfh_inv(idx, 48, n, k);
        g_winF[idx] = __float2half_rn(W_in[(size_t)k * EE + n]);
    } else if (blk < PB_WOL) {
        int idx = (blk - PB_WIN) * 384 + tid;
        int n, k; bfh_inv(idx, 48, n, k);
        g_wolF[idx] = __float2half_rn(W_out[(size_t)k * DM + n]);
    } else if (blk < PB_XPL) {
        int idx = (blk - PB_WOL) * 384 + tid;
        int r, k; afh_inv(idx, 48, r, k);
        g_xplF[idx] = __float2half_rn(W_xp[(size_t)r * (DM + DS) + k]);
    } else if (blk < PB_WPS) {
        int idx = (blk - PB_XPL) * 384 + tid;
        int n, k; bfh_inv(idx, 96, n, k);
        float v = (n < DS)     ? W_xp[(size_t)k * (DM + DS) + DM + n]
                : (n < 2 * DS) ? W_dt[(size_t)k * DS + (n - DS)]
                : 0.0f;
        g_wpsF[idx] = __float2half_rn(v);
        if (blk == PB_XPL && tid < 32)
            g_bias32[tid] = (tid < DS) ? b_xp[DM + tid] : b_dt[tid - DS];
    } else if (blk < PB_WUS2) {
        float (*red)[16][32] = (float (*)[16][32])sh;
        int bb = blk - PB_WPS;
        if (tid < 256) {
            int n = bb * 32 + (tid & 31);
            int chunk = tid >> 5;
            float acc[16];
            #pragma unroll
            for (int s = 0; s < 16; s++) acc[s] = 0.0f;
            for (int j = chunk * 96; j < chunk * 96 + 96; j++) {
                float wo = W_out[(size_t)j * DM + n];
                #pragma unroll
                for (int s = 0; s < 16; s++)
                    acc[s] = fmaf(W_us[(size_t)s * DM + j], wo, acc[s]);
            }
            #pragma unroll
            for (int s = 0; s < 16; s++) red[chunk][s][tid & 31] = acc[s];
        }
        __syncthreads();
        for (int o = tid; o < 512; o += 384) {
            int s = o >> 5, ln = o & 31;
            float t = 0.0f;
            #pragma unroll
            for (int c = 0; c < 8; c++) t += red[c][s][ln];
            int nn = bb * 32 + ln;
            g_comboF[bfh_idx(nn, EE + s,          KC_CAT)] = __float2half_rn(t);
            g_comboF[bfh_idx(nn, EE + DS + s,     KC_CAT)] = __half(0.0f);
            g_comboF[bfh_idx(nn, EE + 2 * DS + s, KC_CAT)] = __half(0.0f);
            g_comboF[bfh_idx(nn, EE + 3 * DS + s, KC_CAT)] = __half(0.0f);
        }
    } else {
        int n = (blk - PB_WUS2) * 384 + tid;
        if (n < DM) {
            float acc = b_out[n];
            for (int j = 0; j < DM; j++)
                acc = fmaf(b_xp[j] + b_us[j], W_out[(size_t)j * DM + n], acc);
            g_cbias[n] = acc;
        }
    }
}

// ======================= depthwise conv (k=4) + SiLU, 8 rows x 2 channels ===
__global__ void conv_silu_kernel(const float* __restrict__ b_conv,
                                 const float* __restrict__ W_conv) {
    int idx = blockIdx.x * blockDim.x + threadIdx.x;
    if (idx >= (NROWS / 8) * (EE / 2)) return;
    int ep = idx % (EE / 2);
    int e0 = ep * 2;
    int r0 = (idx / (EE / 2)) * 8;
    int l0 = r0 % Lseq;
    const __half2* xin2 = (const __half2*)g_xin;

    float2 xa[11];
    #pragma unroll
    for (int j = 0; j < 3; j++) {
        if (l0 >= 3 - j) xa[j] = __half22float2(xin2[(size_t)(r0 - 3 + j) * (EE/2) + ep]);
        else             xa[j] = make_float2(0.f, 0.f);
    }
    #pragma unroll
    for (int j = 3; j < 11; j++)
        xa[j] = __half22float2(xin2[(size_t)(r0 - 3 + j) * (EE/2) + ep]);

    float4 wA = *(const float4*)(W_conv + e0 * 4);
    float4 wB = *(const float4*)(W_conv + e0 * 4 + 4);
    float bc0 = b_conv[e0], bc1 = b_conv[e0 + 1];

    // rows r0..r0+7 share the A-block (r0 % 8 == 0): offset = base + i*32
    __half* outb = g_cat + afh_idx(r0, e0, KC_CAT);
    #pragma unroll
    for (int i = 0; i < 8; i++) {
        float sx = bc0 + xa[i].x * wA.x + xa[i+1].x * wA.y + xa[i+2].x * wA.z + xa[i+3].x * wA.w;
        float sy = bc1 + xa[i].y * wB.x + xa[i+1].y * wB.y + xa[i+2].y * wB.z + xa[i+3].y * wB.w;
        float ax = sx / (1.0f + __expf(-sx));
        float ay = sy / (1.0f + __expf(-sy));
        *(__half2*)(outb + i * 32) = __floats2half2_rn(ax, ay);
    }
}

// ======================= fused prescan + scan + us ==========================
__global__ __launch_bounds__(256) void scan_kernel() {
    int chan = blockIdx.x;
    int bb = chan / DS, s = chan % DS;
    int t = threadIdx.x;
    __shared__ float sA[256], sB[256];
    float A = 1.0f, Bl = 0.0f;
    int base = bb * Lseq;
    #pragma unroll 4
    for (int i = 0; i < 16; i++) {
        size_t rofs = (size_t)(base + t * 16 + i);
        float ds = 0.0f, dtraw = 0.0f;
        #pragma unroll
        for (int z = 0; z < XD_ZS; z++) {
            ds    += g_xd[(size_t)z * NROWS * 32 + rofs * 32 + s];
            dtraw += g_xd[(size_t)z * NROWS * 32 + rofs * 32 + 16 + s];
        }
        float dt = fmaxf(dtraw, 0.0f) + log1pf(__expf(-fabsf(dtraw)));
        float bt = ds * __expf(-0.5f * dt);
        g_dt[rofs * DS + s] = dt;
        g_bt[rofs * DS + s] = bt;
        float a = __expf(-dt);
        Bl = a * Bl + bt;
        A = a * A;
    }
    sA[t] = A; sB[t] = Bl;
    __syncthreads();
    for (int offp = 1; offp < 256; offp <<= 1) {
        float pA = 0.f, pB = 0.f;
        bool has = (t >= offp);
        if (has) { pA = sA[t - offp]; pB = sB[t - offp]; }
        __syncthreads();
        if (has) { sB[t] = sA[t] * pB + sB[t]; sA[t] = sA[t] * pA; }
        __syncthreads();
    }
    float v = (t == 0) ? 0.0f : sB[t - 1];
    for (int i = 0; i < 16; i++) {
        int l = t * 16 + i;
        int row = base + l;
        size_t off = (size_t)row * DS + s;
        float dt = g_dt[off];
        float bt = g_bt[off];
        v = __expf(-dt) * v + bt;
        float kf = (float)(Lseq - 1 - l);
        float denom = expm1f(-dt);
        if (denom > -1e-30f) denom = -1e-30f;
        float us = __expf(-kf * dt) * v + bt * expm1f(-kf * dt) / denom;
        g_cat[afh_idx(row, EE + s,          KC_CAT)] = __float2half_rn(us);
        g_cat[afh_idx(row, EE + DS + s,     KC_CAT)] = __half(0.0f);
        g_cat[afh_idx(row, EE + 2 * DS + s, KC_CAT)] = __half(0.0f);
        g_cat[afh_idx(row, EE + 3 * DS + s, KC_CAT)] = __half(0.0f);
    }
}

// ======================= launch =============================================
extern "C" void kernel_launch(void* const* d_in, const int* in_sizes, int n_in,
                              void* d_out, int out_size) {
    const float* x      = (const float*)d_in[0];
    const float* ln_g   = (const float*)d_in[1];
    const float* ln_b   = (const float*)d_in[2];
    const float* W_in   = (const float*)d_in[3];
    const float* b_in   = (const float*)d_in[4];
    const float* W_conv = (const float*)d_in[5];
    const float* b_conv = (const float*)d_in[6];
    const float* W_xp   = (const float*)d_in[7];
    const float* b_xp   = (const float*)d_in[8];
    const float* W_dt   = (const float*)d_in[9];
    const float* b_dt   = (const float*)d_in[10];
    const float* W_us   = (const float*)d_in[11];
    const float* b_us   = (const float*)d_in[12];
    const float* W_out  = (const float*)d_in[13];
    const float* b_out  = (const float*)d_in[14];
    float* out = (float*)d_out;

    __half *xn, *xin, *cat, *winF, *wpsF, *xplF, *wolF, *comboF;
    float *xd, *bias32, *cbias;
    cudaGetSymbolAddress((void**)&xn,     g_xn);
    cudaGetSymbolAddress((void**)&xin,    g_xin);
    cudaGetSymbolAddress((void**)&cat,    g_cat);
    cudaGetSymbolAddress((void**)&xd,     g_xd);
    cudaGetSymbolAddress((void**)&bias32, g_bias32);
    cudaGetSymbolAddress((void**)&cbias,  g_cbias);
    cudaGetSymbolAddress((void**)&winF,   g_winF);
    cudaGetSymbolAddress((void**)&wpsF,   g_wpsF);
    cudaGetSymbolAddress((void**)&xplF,   g_xplF);
    cudaGetSymbolAddress((void**)&wolF,   g_wolF);
    cudaGetSymbolAddress((void**)&comboF, g_comboF);

    cudaFuncSetAttribute(gemm_f16_kernel<0>, cudaFuncAttributeMaxDynamicSharedMemorySize, GEMM_SMEM);
    cudaFuncSetAttribute(gemm_f16_kernel<1>, cudaFuncAttributeMaxDynamicSharedMemorySize, GEMM_SMEM);
    cudaFuncSetAttribute(gemm_f16_kernel<2>, cudaFuncAttributeMaxDynamicSharedMemorySize, GEMM_SMEM);

    // 1. merged weight prep + LayerNorm
    prep_ln_kernel<<<PB_TOTAL, 384>>>(W_in, W_out, W_xp, W_dt, W_us,
                                      b_xp, b_dt, b_us, b_out,
                                      x, ln_g, ln_b);

    // 2. W_combo rows [0,1536): xplF @ wolF^T + W_out_hi -> comboF (MODE 2)
    gemm_f16_kernel<2><<<dim3(DM/128, EE/128, 1), 256, GEMM_SMEM>>>(
        xplF, 48, wolF, nullptr, comboF, 0, DM, DM, W_out, 0);

    // 3. in-proj: (8192x768)@(768x1536) -> xin fp16 row-major
    gemm_f16_kernel<1><<<dim3(EE/128, NROWS/128, 1), 256, GEMM_SMEM>>>(
        xn, 48, winF, b_in, xin, EE, EE, DM, nullptr, 0);

    // 4. conv + silu -> g_cat A_f (k-blocks 0..95)
    conv_silu_kernel<<<((NROWS/8) * (EE/2) + 255) / 256, 256>>>(b_conv, W_conv);

    // 5. small proj: (8192x1536)@(1536x32) -> xd, K split over grid.z=4
    gemm_f16_kernel<0><<<dim3(1, NROWS/128, XD_ZS), 256, GEMM_SMEM>>>(
        cat, KC_CAT, wpsF, bias32, xd, 32, 32, EE, nullptr,
        (size_t)NROWS * 32 * sizeof(float));

    // 6. fused prescan + scan + us -> g_cat k-blocks 96..99
    scan_kernel<<<Bsz * DS, 256>>>();

    // 7. final: (8192x1600)@(1600x768) + cbias -> out
    gemm_f16_kernel<0><<<dim3(DM/128, NROWS/128, 1), 256, GEMM_SMEM>>>(
        cat, KC_CAT, comboF, cbias, out, DM, DM, KCAT, nullptr, 0);
}

// round 16
// speedup vs baseline: 1.4452x; 1.2003x over previous
#include <cuda_runtime.h>
#include <cuda_fp16.h>
#include <cstdint>
#include <math.h>

#define Bsz 2
#define Lseq 4096
#define DM 768
#define DS 16
#define EE 1536
#define NROWS (Bsz*Lseq)      // 8192
#define KCAT 1600             // 1536 (xact) + 16 (us) + 48 (zero pad)
#define KC_CAT 100            // KCAT/16
#define LN_EPS 1e-5f
#define XD_ZS 4               // K-split factor for small proj

#define STAGE_BYTES 32768     // A tile 16KB + B tile 16KB (K-chunk 64, fp16)
#define GEMM_SMEM (3 * STAGE_BYTES)

// prep_main (default stream): winF then LN rows. 384 threads.
#define PM_WIN   3072         // EE*DM/384
#define PM_TOTAL (PM_WIN + NROWS)

// prep_side (side stream): wolF | xplF | wpsF | wus2 | cbias | zerocat
#define PS_WOL  1536          // DM*DM/384
#define PS_XPL  (PS_WOL + 3072)
#define PS_WPS  (PS_XPL + 512)
#define PS_WUS2 (PS_WPS + 24)
#define PS_CB   (PS_WUS2 + 2)
#define PS_ZC   (PS_CB + 1024)   // 512 panels * 3 blocks * 256 halfs / 384

// ======================= small PTX helpers ==================================
__device__ __forceinline__ uint32_t smem_u32(const void* p) {
    uint32_t a;
    asm("{ .reg .u64 t; cvta.to.shared.u64 t, %1; cvt.u32.u64 %0, t; }"
        : "=r"(a) : "l"(p));
    return a;
}
__device__ __forceinline__ void cp_async16(uint32_t dst, const void* src) {
    asm volatile("cp.async.cg.shared.global [%0], [%1], 16;"
                 :: "r"(dst), "l"(src) : "memory");
}
__device__ __forceinline__ void cp_commit() {
    asm volatile("cp.async.commit_group;" ::: "memory");
}
template<int N> __device__ __forceinline__ void cp_wait() {
    asm volatile("cp.async.wait_group %0;" :: "n"(N) : "memory");
}
__device__ __forceinline__ void mma_f16(float* c, const uint32_t* a, const uint32_t* b) {
    asm volatile("mma.sync.aligned.m16n8k16.row.col.f32.f16.f16.f32 "
        "{%0,%1,%2,%3}, {%4,%5,%6,%7}, {%8,%9}, {%0,%1,%2,%3};"
        : "+f"(c[0]), "+f"(c[1]), "+f"(c[2]), "+f"(c[3])
        : "r"(a[0]), "r"(a[1]), "r"(a[2]), "r"(a[3]), "r"(b[0]), "r"(b[1]));
}

// ---- fp16 fragment-native layouts (half-element index) ----------------------
__device__ __forceinline__ size_t afh_idx(int r, int k, int KC16) {
    size_t blk = (size_t)((r >> 4) * KC16 + (k >> 4));
    int b32 = (r & 7) * 16 + ((k >> 1) & 3) * 4 + ((r >> 3) & 1) + 2 * ((k >> 3) & 1);
    return blk * 256 + b32 * 2 + (k & 1);
}
__device__ __forceinline__ void afh_inv(int idx, int KC16, int& r, int& k) {
    int blk = idx >> 8;
    int b32 = (idx & 255) >> 1, h = idx & 1;
    r = (blk / KC16) * 16 + ((b32 & 1) << 3) + (b32 >> 4);
    k = ((blk % KC16) << 4) | (((b32 >> 1) & 1) << 3) | (((b32 >> 2) & 3) << 1) | h;
}
__device__ __forceinline__ size_t bfh_idx(int n, int k, int KC16) {
    size_t blk = (size_t)((n >> 3) * KC16 + (k >> 4));
    int b32 = (n & 7) * 8 + ((k >> 1) & 3) * 2 + ((k >> 3) & 1);
    return blk * 128 + b32 * 2 + (k & 1);
}
__device__ __forceinline__ void bfh_inv(int idx, int KC16, int& n, int& k) {
    int blk = idx >> 7;
    int b32 = (idx & 127) >> 1, h = idx & 1;
    n = (blk / KC16) * 8 + (b32 >> 3);
    k = ((blk % KC16) << 4) | ((b32 & 1) << 3) | (((b32 >> 1) & 3) << 1) | h;
}

// ======================= scratch ============================================
__device__ __align__(256) __half g_xn    [NROWS * DM];     // A_f (K=768)
__device__ __align__(256) __half g_xin   [NROWS * EE];     // fp16 row-major
__device__ __align__(256) __half g_cat   [NROWS * KCAT];   // A_f: xact|us|0
__device__ __align__(256) float  g_xd    [XD_ZS * NROWS * 32]; // ds|dt_raw partials
__device__ float g_dt [NROWS * DS];
__device__ float g_bt [NROWS * DS];
__device__ float g_bias32[32];
__device__ float g_cbias [DM];
__device__ __align__(256) __half g_winF  [EE * DM];        // B_f: N=1536, K=768
__device__ __align__(256) __half g_wpsF  [128 * EE];       // B_f: N=128(pad), K=1536
__device__ __align__(256) __half g_xplF  [EE * DM];        // A_f: W_xp_low (M=1536,K=768)
__device__ __align__(256) __half g_wolF  [DM * DM];        // B_f: W_out_low (N=768,K=768)
__device__ __align__(256) __half g_comboF[(DM/8) * KC_CAT * 128]; // B_f: N=768, K=1600

// ======================= fp16 mma.sync GEMM (R10 champion) ==================
template<int MODE>
__global__ __launch_bounds__(256, 2) void gemm_f16_kernel(
    const __half* __restrict__ Af, int kc16s,
    const __half* __restrict__ Bf,
    const float* __restrict__ bias, void* __restrict__ Cv,
    int ldc, int Ndim, int K, const float* __restrict__ addW,
    size_t zstride)
{
    extern __shared__ __align__(16) char sm[];
    const int tid = threadIdx.x;
    const int wid = tid >> 5, lane = tid & 31;
    const int wm = wid >> 1, wn = wid & 1;
    const int g = lane >> 2, tg = lane & 3;
    const int KC16 = K >> 4;
    const int NCz = (K >> 6) / gridDim.z;
    const int c0 = blockIdx.z * NCz;
    const int mp0 = blockIdx.y * 8;
    const int ng0 = blockIdx.x * 16;
    const int m0 = blockIdx.y * 128, n0 = blockIdx.x * 128;
    const uint32_t smb = smem_u32(sm);

    auto load_chunk = [&](int i) {
        const int c = c0 + i;
        const uint32_t st = (uint32_t)(i % 3) * STAGE_BYTES;
        #pragma unroll
        for (int j = 0; j < 4; j++) {
            int L = tid + 256 * j;
            int pp = L >> 7, qq = (L >> 5) & 3, ll = L & 31;
            const __half* src = Af + ((size_t)(mp0 + pp) * kc16s + 4 * c + qq) * 256 + ll * 8;
            cp_async16(smb + st + (uint32_t)((pp * 4 + qq) * 512 + ll * 16), src);
        }
        #pragma unroll
        for (int j = 0; j < 4; j++) {
            int L = tid + 256 * j;
            int ng = L >> 6, qq = (L >> 4) & 3, ll = L & 15;
            const __half* src = Bf + ((size_t)(ng0 + ng) * KC16 + 4 * c + qq) * 128 + ll * 8;
            cp_async16(smb + st + 16384u + (uint32_t)((ng * 4 + qq) * 256 + ll * 16), src);
        }
        cp_commit();
    };

    float acc[2][8][4];
    #pragma unroll
    for (int mi = 0; mi < 2; mi++)
        #pragma unroll
        for (int ni = 0; ni < 8; ni++)
            #pragma unroll
            for (int q = 0; q < 4; q++) acc[mi][ni][q] = 0.0f;

    load_chunk(0); load_chunk(1);

    const char* stA_w = sm + wm * 4096 + g * 64 + tg * 16;
    const char* stB_w = sm + 16384 + wn * 8192 + g * 32 + tg * 8;

    for (int i = 0; i < NCz; i++) {
        cp_wait<1>();
        __syncthreads();
        if (i + 2 < NCz) load_chunk(i + 2); else cp_commit();

        const char* stA = stA_w + (i % 3) * STAGE_BYTES;
        const char* stB = stB_w + (i % 3) * STAGE_BYTES;

        #pragma unroll
        for (int kb = 0; kb < 4; kb++) {
            uint4 a0 = *(const uint4*)(stA + kb * 512);
            uint4 a1 = *(const uint4*)(stA + 2048 + kb * 512);
            uint2 bq[8];
            #pragma unroll
            for (int ni = 0; ni < 8; ni++)
                bq[ni] = *(const uint2*)(stB + ni * 1024 + kb * 256);
            #pragma unroll
            for (int ni = 0; ni < 8; ni++) {
                mma_f16(acc[0][ni], (const uint32_t*)&a0, (const uint32_t*)&bq[ni]);
                mma_f16(acc[1][ni], (const uint32_t*)&a1, (const uint32_t*)&bq[ni]);
            }
        }
    }

    if (MODE == 2) {
        __half* Cc = (__half*)Cv;
        #pragma unroll
        for (int mi = 0; mi < 2; mi++)
            #pragma unroll
            for (int ni = 0; ni < 8; ni++)
                #pragma unroll
                for (int q = 0; q < 4; q++) {
                    int row = m0 + wm * 32 + mi * 16 + g + ((q >> 1) << 3);
                    int col = n0 + wn * 64 + ni * 8 + tg * 2 + (q & 1);
                    float v = acc[mi][ni][q];
                    if (row >= DM) v += addW[(size_t)row * DM + col];
                    Cc[bfh_idx(col, row, KC_CAT)] = __float2half_rn(v);
                }
    } else {
        const bool ub = (blockIdx.z == 0);
        char* Cz = (char*)Cv + (size_t)blockIdx.z * zstride;
        #pragma unroll
        for (int mi = 0; mi < 2; mi++) {
            const int row = m0 + wm * 32 + mi * 16 + g;
            #pragma unroll
            for (int ni = 0; ni < 8; ni++) {
                const int col = n0 + wn * 64 + ni * 8 + tg * 2;
                if (col < Ndim) {
                    float bx = ub ? bias[col] : 0.0f;
                    float by = ub ? bias[col + 1] : 0.0f;
                    float v00 = acc[mi][ni][0] + bx, v01 = acc[mi][ni][1] + by;
                    float v10 = acc[mi][ni][2] + bx, v11 = acc[mi][ni][3] + by;
                    if (MODE == 1) {
                        __half* c0 = (__half*)Cz + (size_t)row * ldc;
                        __half* c1 = (__half*)Cz + (size_t)(row + 8) * ldc;
                        *(__half2*)(c0 + col) = __floats2half2_rn(v00, v01);
                        *(__half2*)(c1 + col) = __floats2half2_rn(v10, v11);
                    } else {
                        float* c0 = (float*)Cz + (size_t)row * ldc;
                        float* c1 = (float*)Cz + (size_t)(row + 8) * ldc;
                        *(float2*)(c0 + col) = make_float2(v00, v01);
                        *(float2*)(c1 + col) = make_float2(v10, v11);
                    }
                }
            }
        }
    }
}

// ======================= prep_main: winF + LayerNorm ========================
__global__ __launch_bounds__(384) void prep_main_kernel(
    const float* __restrict__ W_in,
    const float* __restrict__ x,
    const float* __restrict__ ln_g,
    const float* __restrict__ ln_b)
{
    __shared__ float sh[512];
    const int blk = blockIdx.x;
    const int tid = threadIdx.x;

    if (blk < PM_WIN) {
        int idx = blk * 384 + tid;
        int n, k; bfh_inv(idx, 48, n, k);
        g_winF[idx] = __float2half_rn(W_in[(size_t)k * EE + n]);
        return;
    }
    int row = blk - PM_WIN;
    const float2* xr = (const float2*)(x + (size_t)row * DM);
    float2 v = xr[tid];
    if (tid < 128) sh[384 + tid] = 0.0f;
    sh[tid] = v.x + v.y;
    __syncthreads();
    for (int off = 256; off > 0; off >>= 1) {
        if (tid < off) sh[tid] += sh[tid + off];
        __syncthreads();
    }
    float mu = sh[0] * (1.0f / DM);
    __syncthreads();
    float dx = v.x - mu, dy = v.y - mu;
    sh[tid] = dx * dx + dy * dy;
    __syncthreads();
    for (int off = 256; off > 0; off >>= 1) {
        if (tid < off) sh[tid] += sh[tid + off];
        __syncthreads();
    }
    float rstd = rsqrtf(sh[0] * (1.0f / DM) + LN_EPS);
    float2 gg = ((const float2*)ln_g)[tid];
    float2 bb = ((const float2*)ln_b)[tid];
    float h0 = dx * rstd * gg.x + bb.x;
    float h1 = dy * rstd * gg.y + bb.y;
    *(__half2*)(g_xn + afh_idx(row, 2 * tid, 48)) = __floats2half2_rn(h0, h1);
}

// ======================= prep_side: other weights + zero pad ================
__global__ __launch_bounds__(384) void prep_side_kernel(
    const float* __restrict__ W_out,
    const float* __restrict__ W_xp,
    const float* __restrict__ W_dt,
    const float* __restrict__ W_us,
    const float* __restrict__ b_xp,
    const float* __restrict__ b_dt,
    const float* __restrict__ b_us,
    const float* __restrict__ b_out)
{
    __shared__ float red[8][16][32];
    const int blk = blockIdx.x;
    const int tid = threadIdx.x;

    if (blk < PS_WOL) {
        int idx = blk * 384 + tid;
        int n, k; bfh_inv(idx, 48, n, k);
        g_wolF[idx] = __float2half_rn(W_out[(size_t)k * DM + n]);
    } else if (blk < PS_XPL) {
        int idx = (blk - PS_WOL) * 384 + tid;
        int r, k; afh_inv(idx, 48, r, k);
        g_xplF[idx] = __float2half_rn(W_xp[(size_t)r * (DM + DS) + k]);
    } else if (blk < PS_WPS) {
        int idx = (blk - PS_XPL) * 384 + tid;
        int n, k; bfh_inv(idx, 96, n, k);
        float v = (n < DS)     ? W_xp[(size_t)k * (DM + DS) + DM + n]
                : (n < 2 * DS) ? W_dt[(size_t)k * DS + (n - DS)]
                : 0.0f;
        g_wpsF[idx] = __float2half_rn(v);
        if (blk == PS_XPL && tid < 32)
            g_bias32[tid] = (tid < DS) ? b_xp[DM + tid] : b_dt[tid - DS];
    } else if (blk < PS_WUS2) {
        int bb = blk - PS_WPS;
        if (tid < 256) {
            int n = bb * 32 + (tid & 31);
            int chunk = tid >> 5;
            float acc[16];
            #pragma unroll
            for (int s = 0; s < 16; s++) acc[s] = 0.0f;
            for (int j = chunk * 96; j < chunk * 96 + 96; j++) {
                float wo = W_out[(size_t)j * DM + n];
                #pragma unroll
                for (int s = 0; s < 16; s++)
                    acc[s] = fmaf(W_us[(size_t)s * DM + j], wo, acc[s]);
            }
            #pragma unroll
            for (int s = 0; s < 16; s++) red[chunk][s][tid & 31] = acc[s];
        }
        __syncthreads();
        for (int o = tid; o < 512; o += 384) {
            int s = o >> 5, ln = o & 31;
            float t = 0.0f;
            #pragma unroll
            for (int c = 0; c < 8; c++) t += red[c][s][ln];
            int nn = bb * 32 + ln;
            g_comboF[bfh_idx(nn, EE + s,          KC_CAT)] = __float2half_rn(t);
            g_comboF[bfh_idx(nn, EE + DS + s,     KC_CAT)] = __half(0.0f);
            g_comboF[bfh_idx(nn, EE + 2 * DS + s, KC_CAT)] = __half(0.0f);
            g_comboF[bfh_idx(nn, EE + 3 * DS + s, KC_CAT)] = __half(0.0f);
        }
    } else if (blk < PS_CB) {
        int n = (blk - PS_WUS2) * 384 + tid;
        if (n < DM) {
            float acc = b_out[n];
            for (int j = 0; j < DM; j++)
                acc = fmaf(b_xp[j] + b_us[j], W_out[(size_t)j * DM + n], acc);
            g_cbias[n] = acc;
        }
    } else {
        // zero g_cat k-blocks 97..99 for all 512 row panels
        int idx = (blk - PS_CB) * 384 + tid;   // < 512*3*256 = 393216
        int panel = idx / 768;
        int rem = idx % 768;
        int kb = 97 + (rem >> 8);
        g_cat[((size_t)panel * KC_CAT + kb) * 256 + (rem & 255)] = __half(0.0f);
    }
}

// ======================= depthwise conv (k=4) + SiLU, 8 rows x 2 channels ===
__global__ void conv_silu_kernel(const float* __restrict__ b_conv,
                                 const float* __restrict__ W_conv) {
    int idx = blockIdx.x * blockDim.x + threadIdx.x;
    if (idx >= (NROWS / 8) * (EE / 2)) return;
    int ep = idx % (EE / 2);
    int e0 = ep * 2;
    int r0 = (idx / (EE / 2)) * 8;
    int l0 = r0 % Lseq;
    const __half2* xin2 = (const __half2*)g_xin;

    float2 xa[11];
    #pragma unroll
    for (int j = 0; j < 3; j++) {
        if (l0 >= 3 - j) xa[j] = __half22float2(xin2[(size_t)(r0 - 3 + j) * (EE/2) + ep]);
        else             xa[j] = make_float2(0.f, 0.f);
    }
    #pragma unroll
    for (int j = 3; j < 11; j++)
        xa[j] = __half22float2(xin2[(size_t)(r0 - 3 + j) * (EE/2) + ep]);

    float4 wA = *(const float4*)(W_conv + e0 * 4);
    float4 wB = *(const float4*)(W_conv + e0 * 4 + 4);
    float bc0 = b_conv[e0], bc1 = b_conv[e0 + 1];

    __half* outb = g_cat + afh_idx(r0, e0, KC_CAT);
    #pragma unroll
    for (int i = 0; i < 8; i++) {
        float sx = bc0 + xa[i].x * wA.x + xa[i+1].x * wA.y + xa[i+2].x * wA.z + xa[i+3].x * wA.w;
        float sy = bc1 + xa[i].y * wB.x + xa[i+1].y * wB.y + xa[i+2].y * wB.z + xa[i+3].y * wB.w;
        float ax = sx / (1.0f + __expf(-sx));
        float ay = sy / (1.0f + __expf(-sy));
        *(__half2*)(outb + i * 32) = __floats2half2_rn(ax, ay);
    }
}

// ======================= fused prescan + scan + us ==========================
__global__ __launch_bounds__(256) void scan_kernel() {
    int chan = blockIdx.x;
    int bb = chan / DS, s = chan % DS;
    int t = threadIdx.x;
    __shared__ float sA[256], sB[256];
    float A = 1.0f, Bl = 0.0f;
    int base = bb * Lseq;
    #pragma unroll 4
    for (int i = 0; i < 16; i++) {
        size_t rofs = (size_t)(base + t * 16 + i);
        float ds = 0.0f, dtraw = 0.0f;
        #pragma unroll
        for (int z = 0; z < XD_ZS; z++) {
            ds    += g_xd[(size_t)z * NROWS * 32 + rofs * 32 + s];
            dtraw += g_xd[(size_t)z * NROWS * 32 + rofs * 32 + 16 + s];
        }
        float dt = fmaxf(dtraw, 0.0f) + log1pf(__expf(-fabsf(dtraw)));
        float bt = ds * __expf(-0.5f * dt);
        g_dt[rofs * DS + s] = dt;
        g_bt[rofs * DS + s] = bt;
        float a = __expf(-dt);
        Bl = a * Bl + bt;
        A = a * A;
    }
    sA[t] = A; sB[t] = Bl;
    __syncthreads();
    for (int offp = 1; offp < 256; offp <<= 1) {
        float pA = 0.f, pB = 0.f;
        bool has = (t >= offp);
        if (has) { pA = sA[t - offp]; pB = sB[t - offp]; }
        __syncthreads();
        if (has) { sB[t] = sA[t] * pB + sB[t]; sA[t] = sA[t] * pA; }
        __syncthreads();
    }
    float v = (t == 0) ? 0.0f : sB[t - 1];
    for (int i = 0; i < 16; i++) {
        int l = t * 16 + i;
        int row = base + l;
        size_t off = (size_t)row * DS + s;
        float dt = g_dt[off];
        float bt = g_bt[off];
        v = __expf(-dt) * v + bt;
        float kf = (float)(Lseq - 1 - l);
        float denom = expm1f(-dt);
        if (denom > -1e-30f) denom = -1e-30f;
        float us = __expf(-kf * dt) * v + bt * expm1f(-kf * dt) / denom;
        g_cat[afh_idx(row, EE + s, KC_CAT)] = __float2half_rn(us);
    }
}

// ======================= launch =============================================
extern "C" void kernel_launch(void* const* d_in, const int* in_sizes, int n_in,
                              void* d_out, int out_size) {
    const float* x      = (const float*)d_in[0];
    const float* ln_g   = (const float*)d_in[1];
    const float* ln_b   = (const float*)d_in[2];
    const float* W_in   = (const float*)d_in[3];
    const float* b_in   = (const float*)d_in[4];
    const float* W_conv = (const float*)d_in[5];
    const float* b_conv = (const float*)d_in[6];
    const float* W_xp   = (const float*)d_in[7];
    const float* b_xp   = (const float*)d_in[8];
    const float* W_dt   = (const float*)d_in[9];
    const float* b_dt   = (const float*)d_in[10];
    const float* W_us   = (const float*)d_in[11];
    const float* b_us   = (const float*)d_in[12];
    const float* W_out  = (const float*)d_in[13];
    const float* b_out  = (const float*)d_in[14];
    float* out = (float*)d_out;

    __half *xn, *xin, *cat, *winF, *wpsF, *xplF, *wolF, *comboF;
    float *xd, *bias32, *cbias;
    cudaGetSymbolAddress((void**)&xn,     g_xn);
    cudaGetSymbolAddress((void**)&xin,    g_xin);
    cudaGetSymbolAddress((void**)&cat,    g_cat);
    cudaGetSymbolAddress((void**)&xd,     g_xd);
    cudaGetSymbolAddress((void**)&bias32, g_bias32);
    cudaGetSymbolAddress((void**)&cbias,  g_cbias);
    cudaGetSymbolAddress((void**)&winF,   g_winF);
    cudaGetSymbolAddress((void**)&wpsF,   g_wpsF);
    cudaGetSymbolAddress((void**)&xplF,   g_xplF);
    cudaGetSymbolAddress((void**)&wolF,   g_wolF);
    cudaGetSymbolAddress((void**)&comboF, g_comboF);

    static cudaStream_t s1 = nullptr;
    static cudaEvent_t evFork = nullptr, evJoin = nullptr;
    if (!s1) {
        cudaStreamCreateWithFlags(&s1, cudaStreamNonBlocking);
        cudaEventCreateWithFlags(&evFork, cudaEventDisableTiming);
        cudaEventCreateWithFlags(&evJoin, cudaEventDisableTiming);
        cudaFuncSetAttribute(gemm_f16_kernel<0>, cudaFuncAttributeMaxDynamicSharedMemorySize, GEMM_SMEM);
        cudaFuncSetAttribute(gemm_f16_kernel<1>, cudaFuncAttributeMaxDynamicSharedMemorySize, GEMM_SMEM);
        cudaFuncSetAttribute(gemm_f16_kernel<2>, cudaFuncAttributeMaxDynamicSharedMemorySize, GEMM_SMEM);
    }

    // fork side stream off the capturing stream
    cudaEventRecord(evFork, 0);
    cudaStreamWaitEvent(s1, evFork, 0);

    // side chain: other weight formats + zero pad, then combo GEMM
    prep_side_kernel<<<PS_ZC, 384, 0, s1>>>(W_out, W_xp, W_dt, W_us,
                                            b_xp, b_dt, b_us, b_out);
    gemm_f16_kernel<2><<<dim3(DM/128, EE/128, 1), 256, GEMM_SMEM, s1>>>(
        xplF, 48, wolF, nullptr, comboF, 0, DM, DM, W_out, 0);

    // main chain
    prep_main_kernel<<<PM_TOTAL, 384>>>(W_in, x, ln_g, ln_b);
    gemm_f16_kernel<1><<<dim3(EE/128, NROWS/128, 1), 256, GEMM_SMEM>>>(
        xn, 48, winF, b_in, xin, EE, EE, DM, nullptr, 0);
    conv_silu_kernel<<<((NROWS/8) * (EE/2) + 255) / 256, 256>>>(b_conv, W_conv);

    // join side stream (wpsF/comboF/cbias/zero-pad ready)
    cudaEventRecord(evJoin, s1);
    cudaStreamWaitEvent(0, evJoin, 0);

    // small proj: (8192x1536)@(1536x32) -> xd, K split over grid.z=4
    gemm_f16_kernel<0><<<dim3(1, NROWS/128, XD_ZS), 256, GEMM_SMEM>>>(
        cat, KC_CAT, wpsF, bias32, xd, 32, 32, EE, nullptr,
        (size_t)NROWS * 32 * sizeof(float));

    // fused prescan + scan + us -> g_cat k-block 96
    scan_kernel<<<Bsz * DS, 256>>>();

    // final: (8192x1600)@(1600x768) + cbias -> out
    gemm_f16_kernel<0><<<dim3(DM/128, NROWS/128, 1), 256, GEMM_SMEM>>>(
        cat, KC_CAT, comboF, cbias, out, DM, DM, KCAT, nullptr, 0);
}